// round 2
// baseline (speedup 1.0000x reference)
#include <cuda_runtime.h>
#include <stdint.h>

#define NB 256      // batch
#define NE 512      // entities
#define NC 256      // channels
#define NAR 1024
#define NH 256
#define NK 32
#define NSTEPS 64

// ---------------- static device scratch (no allocations allowed) ----------------
__device__ float g_ar[NB * NAR];                      // 1 MB
__device__ float g_keyproj[(size_t)NB * NE * NK];     // 16 MB
__device__ float g_gumbel[(size_t)NSTEPS * NB * NE];  // 32 MB
__device__ float g_func[NB * NH];                     // 256 KB
__device__ float g_xpart[8 * NB * NH];                // 2 MB (split-K partials)
__device__ float g_mask[NB * NE];                     // 512 KB
__device__ float g_h[NB * NK];
__device__ float g_c[NB * NK];
__device__ uint2 g_subkeys[NSTEPS];
__device__ int   g_action[NB];

// output layout: [units_logits (256*64*512)] [units (256*64)] [ar (256*1024)]
#define OFF_UNITS ((size_t)NB * NSTEPS * NE)          // 8388608
#define OFF_AR    (OFF_UNITS + (size_t)NB * NSTEPS)   // 8404992

// ---------------- Threefry-2x32 (20 rounds), matches JAX ----------------
__device__ __forceinline__ void tf2x32(uint32_t k0, uint32_t k1,
                                       uint32_t x0, uint32_t x1,
                                       uint32_t &o0, uint32_t &o1) {
  uint32_t ks2 = k0 ^ k1 ^ 0x1BD11BDAu;
  x0 += k0; x1 += k1;
#define RND(r) { x0 += x1; x1 = __funnelshift_l(x1, x1, (r)); x1 ^= x0; }
  RND(13) RND(15) RND(26) RND(6)   x0 += k1;  x1 += ks2 + 1u;
  RND(17) RND(29) RND(16) RND(24)  x0 += ks2; x1 += k0  + 2u;
  RND(13) RND(15) RND(26) RND(6)   x0 += k0;  x1 += k1  + 3u;
  RND(17) RND(29) RND(16) RND(24)  x0 += k1;  x1 += ks2 + 4u;
  RND(13) RND(15) RND(26) RND(6)   x0 += ks2; x1 += k0  + 5u;
#undef RND
  o0 = x0; o1 = x1;
}

__device__ __forceinline__ float gumbelize(uint32_t bits) {
  float f = __uint_as_float((bits >> 9) | 0x3f800000u) - 1.0f;
  f = fmaxf(f, 1e-20f);
  return -logf(-logf(f));
}

// ---------------- setup: action dtype detect + key chain ----------------
// JAX partitionable: rng' = tf(key,(0,0)), sub = tf(key,(0,1))
__global__ void setup_kernel(const int* __restrict__ action_raw) {
  // detect int64 vs int32 action_type: if int64, odd int32 words (hi words) are all 0
  bool is64 = true;
  for (int i = 1; i < 256; i += 2) {
    if (action_raw[i] != 0) { is64 = false; break; }
  }
  for (int b = 0; b < NB; b++)
    g_action[b] = is64 ? action_raw[2 * b] : action_raw[b];

  uint32_t k0 = 0u, k1 = 42u;
  for (int s = 0; s < NSTEPS; s++) {
    uint32_t n0, n1, s0, s1;
    tf2x32(k0, k1, 0u, 0u, n0, n1);
    tf2x32(k0, k1, 0u, 1u, s0, s1);
    g_subkeys[s] = make_uint2(s0, s1);
    k0 = n0; k1 = n1;
  }
}

// ---------------- init ar/mask/h/c ----------------
__global__ void init_kernel(const float* __restrict__ ar_in) {
  int i = blockIdx.x * 256 + threadIdx.x;           // 262144 threads
  g_ar[i] = ar_in[i];
  if (i < NB * NE) g_mask[i] = 1.0f;
  if (i < NB * NK) { g_h[i] = 0.0f; g_c[i] = 0.0f; }
}

// ---------------- gumbel table (partitionable random_bits: bits1^bits2) ----------------
__global__ void gumbel_kernel() {
  int j = blockIdx.x * 256 + threadIdx.x;   // 0..131071
  int s = blockIdx.y;                        // 0..63
  uint2 k = g_subkeys[s];
  uint32_t o0, o1;
  tf2x32(k.x, k.y, 0u, (uint32_t)j, o0, o1);
  g_gumbel[(size_t)s * (NB * NE) + j] = gumbelize(o0 ^ o1);
}

// ---------------- func embed: relu(one_hot@Wf + bf) ----------------
__global__ void func_kernel(const float* __restrict__ Wf, const float* __restrict__ bf,
                            const float* __restrict__ table) {
  int b = blockIdx.x, j = threadIdx.x;
  int a = g_action[b];
  const float* tr = table + (size_t)a * 256;
  float acc = bf[j];
  #pragma unroll 4
  for (int k = 0; k < 256; k++) acc += tr[k] * Wf[k * 256 + j];
  g_func[b * 256 + j] = fmaxf(acc, 0.0f);
}

// ---------------- key_proj = emb @ Wk + bk ----------------
__global__ void keyproj_kernel(const float* __restrict__ emb, const float* __restrict__ Wk,
                               const float* __restrict__ bk) {
  int row = blockIdx.x * 8 + (threadIdx.x >> 5);    // (b,e) row 0..131071
  int h = threadIdx.x & 31;
  const float* er = emb + (size_t)row * NC;
  float acc = bk[h];
  #pragma unroll 4
  for (int c = 0; c < NC; c++) acc += er[c] * Wk[c * NK + h];
  g_keyproj[(size_t)row * NK + h] = acc;
}

// ---------------- per-step GEMM: xpart[z] = ar[:, z*128:(z+1)*128] @ W1[z*128:,:] ----------------
#define BM 32
#define BN 64
#define BK 16
#define KSL 128
__global__ void gemm_kernel(const float* __restrict__ W1) {
  __shared__ __align__(16) float As[BK][BM + 1];
  __shared__ __align__(16) float Bs[BK][68];
  int bm = blockIdx.y * BM, bn = blockIdx.x * BN, k0 = blockIdx.z * KSL;
  int t = threadIdx.x;
  int ty = t >> 4, tx = t & 15;
  float acc[2][4] = {{0.f,0.f,0.f,0.f},{0.f,0.f,0.f,0.f}};

  for (int kc = 0; kc < KSL; kc += BK) {
    {
      int m = t >> 3;              // 0..31
      int kk = (t & 7) * 2;        // 0..14
      const float* p = g_ar + (size_t)(bm + m) * NAR + (k0 + kc + kk);
      As[kk][m] = p[0];
      As[kk + 1][m] = p[1];
    }
    {
      int kk = t >> 4;             // 0..15
      int j = (t & 15) * 4;        // 0..60
      const float* p = W1 + (size_t)(k0 + kc + kk) * NH + bn + j;
      Bs[kk][j] = p[0]; Bs[kk][j+1] = p[1]; Bs[kk][j+2] = p[2]; Bs[kk][j+3] = p[3];
    }
    __syncthreads();
    #pragma unroll
    for (int k = 0; k < BK; k++) {
      float a0 = As[k][ty * 2], a1 = As[k][ty * 2 + 1];
      float4 bv = *reinterpret_cast<const float4*>(&Bs[k][tx * 4]);
      acc[0][0] += a0 * bv.x; acc[0][1] += a0 * bv.y; acc[0][2] += a0 * bv.z; acc[0][3] += a0 * bv.w;
      acc[1][0] += a1 * bv.x; acc[1][1] += a1 * bv.y; acc[1][2] += a1 * bv.z; acc[1][3] += a1 * bv.w;
    }
    __syncthreads();
  }
  float* xp = g_xpart + (size_t)blockIdx.z * (NB * NH);
  #pragma unroll
  for (int im = 0; im < 2; im++) {
    int row = bm + ty * 2 + im;
    float* o = xp + (size_t)row * NH + bn + tx * 4;
    o[0] = acc[im][0]; o[1] = acc[im][1]; o[2] = acc[im][2]; o[3] = acc[im][3];
  }
}

// ---------------- per-step fused kernel (one block per batch row) ----------------
__device__ __forceinline__ unsigned fenc(float f) {
  unsigned u = __float_as_uint(f);
  return (u & 0x80000000u) ? ~u : (u | 0x80000000u);
}

__global__ void step_kernel(int s,
    const float* __restrict__ b1, const float* __restrict__ W2, const float* __restrict__ b2,
    const float* __restrict__ Wx, const float* __restrict__ Wh, const float* __restrict__ bl,
    const float* __restrict__ Wp, const float* __restrict__ bp,
    const float* __restrict__ selt, float* __restrict__ out)
{
  int b = blockIdx.x, t = threadIdx.x;
  __shared__ float s_t[256];
  __shared__ float s_red[256];
  __shared__ unsigned long long s_key[256];
  __shared__ float s_z2[32], s_z[128], s_h[32], s_hp[32], s_cp[32], s_out[32];

  float sel = selt[g_action[b]];

  if (t < 32) { s_hp[t] = g_h[b * 32 + t]; s_cp[t] = g_c[b * 32 + t]; }

  // phase 1: x = ar@W1 + b1 (sum split-K partials), t = relu(func + x)
  {
    float xv = b1[t];
    #pragma unroll
    for (int p = 0; p < 8; p++) xv += g_xpart[p * (NB * NH) + b * 256 + t];
    s_t[t] = fmaxf(g_func[b * 256 + t] + xv, 0.0f);
  }
  __syncthreads();

  // phase 2a: z2 partials = t @ W2
  {
    int h = t & 31, p = t >> 5;
    float acc = 0.f;
    const float* st = s_t + p * 32;
    const float* w = W2 + (size_t)(p * 32) * 32 + h;
    #pragma unroll
    for (int j = 0; j < 32; j++) acc += st[j] * w[j * 32];
    s_red[t] = acc;
  }
  __syncthreads();
  if (t < 32) {
    float z2 = b2[t];
    #pragma unroll
    for (int p = 0; p < 8; p++) z2 += s_red[p * 32 + t];
    s_z2[t] = z2;
  }
  __syncthreads();
  // phase 2c: LSTM preactivations z = z2@Wx + h@Wh + bl
  if (t < 128) {
    float zv = bl[t];
    #pragma unroll
    for (int k = 0; k < 32; k++) zv += s_z2[k] * Wx[k * 128 + t] + s_hp[k] * Wh[k * 128 + t];
    s_z[t] = zv;
  }
  __syncthreads();
  // phase 2d: gates
  if (t < 32) {
    float iv = 1.f / (1.f + expf(-s_z[t]));
    float fv = 1.f / (1.f + expf(-s_z[32 + t]));
    float gv = tanhf(s_z[64 + t]);
    float ov = 1.f / (1.f + expf(-s_z[96 + t]));
    float cv = fv * s_cp[t] + iv * gv;
    float hv = ov * tanhf(cv);
    g_c[b * 32 + t] = cv; g_h[b * 32 + t] = hv; s_h[t] = hv;
  }
  __syncthreads();

  // phase 3: y = key_proj . h, mask, write logits, softmax + gumbel argmax
  float lmax = -3.0e38f;
  float y2a[2];
  #pragma unroll
  for (int r = 0; r < 2; r++) {
    int e = t + r * 256;
    const float4* kr = reinterpret_cast<const float4*>(g_keyproj + ((size_t)(b * NE + e)) * NK);
    float acc = 0.f;
    #pragma unroll
    for (int q = 0; q < 8; q++) {
      float4 v = kr[q];
      acc += v.x * s_h[4*q] + v.y * s_h[4*q+1] + v.z * s_h[4*q+2] + v.w * s_h[4*q+3];
    }
    float y2 = acc * g_mask[b * NE + e];
    out[((size_t)b * NSTEPS + s) * NE + e] = y2 * sel;
    y2a[r] = y2;
    lmax = fmaxf(lmax, y2);
  }
  s_red[t] = lmax;
  __syncthreads();
  for (int o = 128; o; o >>= 1) { if (t < o) s_red[t] = fmaxf(s_red[t], s_red[t + o]); __syncthreads(); }
  float mx = s_red[0];
  __syncthreads();
  float p0 = expf(y2a[0] - mx), p1 = expf(y2a[1] - mx);
  s_red[t] = p0 + p1;
  __syncthreads();
  for (int o = 128; o; o >>= 1) { if (t < o) s_red[t] += s_red[t + o]; __syncthreads(); }
  float sm = s_red[0];

  {
    const float* gp = g_gumbel + ((size_t)s * NB + b) * NE;
    float v0 = p0 / sm + gp[t];
    float v1 = p1 / sm + gp[t + 256];
    unsigned long long kA = ((unsigned long long)fenc(v0) << 32) | (unsigned long long)(0xFFFFFFFFu - (unsigned)t);
    unsigned long long kB = ((unsigned long long)fenc(v1) << 32) | (unsigned long long)(0xFFFFFFFFu - (unsigned)(t + 256));
    s_key[t] = (kA > kB) ? kA : kB;
  }
  __syncthreads();
  for (int o = 128; o; o >>= 1) { if (t < o) { if (s_key[t + o] > s_key[t]) s_key[t] = s_key[t + o]; } __syncthreads(); }
  int id = (int)(0xFFFFFFFFu - (unsigned)(s_key[0] & 0xFFFFFFFFull));

  // phase 4: mask update, units output, gather key_proj[b,id,:]
  if (t == 0) {
    g_mask[b * NE + id] = 0.0f;
    out[OFF_UNITS + (size_t)b * NSTEPS + s] = (float)id * sel;
  }
  if (t < 32) s_out[t] = g_keyproj[((size_t)(b * NE + id)) * NK + t] - 0.001953125f;  // -1/512
  __syncthreads();

  // phase 5: ar += out @ Wp + bp
  for (int kk = t; kk < NAR; kk += 256) {
    float acc = bp[kk];
    #pragma unroll
    for (int h = 0; h < 32; h++) acc += s_out[h] * Wp[h * NAR + kk];
    float na = g_ar[b * NAR + kk] + acc;
    g_ar[b * NAR + kk] = na;
    if (s == NSTEPS - 1) out[OFF_AR + (size_t)b * NAR + kk] = na * sel;
  }
}

// ---------------- launcher ----------------
extern "C" void kernel_launch(void* const* d_in, const int* in_sizes, int n_in,
                              void* d_out, int out_size) {
  const float* ar_in   = (const float*)d_in[0];
  const int*   action  = (const int*)  d_in[1];
  const float* emb     = (const float*)d_in[2];
  const float* Wf      = (const float*)d_in[3];
  const float* bf      = (const float*)d_in[4];
  const float* Wk      = (const float*)d_in[5];
  const float* bk      = (const float*)d_in[6];
  const float* W1      = (const float*)d_in[7];
  const float* b1      = (const float*)d_in[8];
  const float* W2      = (const float*)d_in[9];
  const float* b2      = (const float*)d_in[10];
  const float* Wx      = (const float*)d_in[11];
  const float* Wh      = (const float*)d_in[12];
  const float* bl      = (const float*)d_in[13];
  const float* Wp      = (const float*)d_in[14];
  const float* bp      = (const float*)d_in[15];
  const float* table   = (const float*)d_in[16];
  const float* selt    = (const float*)d_in[17];
  float* out = (float*)d_out;

  setup_kernel<<<1, 1>>>(action);
  init_kernel<<<1024, 256>>>(ar_in);
  func_kernel<<<256, 256>>>(Wf, bf, table);
  keyproj_kernel<<<16384, 256>>>(emb, Wk, bk);
  gumbel_kernel<<<dim3(512, 64), 256>>>();

  for (int s = 0; s < NSTEPS; s++) {
    gemm_kernel<<<dim3(4, 8, 8), 256>>>(W1);
    step_kernel<<<256, 256>>>(s, b1, W2, b2, Wx, Wh, bl, Wp, bp, selt, out);
  }
}

// round 3
// speedup vs baseline: 2.4897x; 2.4897x over previous
#include <cuda_runtime.h>
#include <stdint.h>

#define NB 256
#define NE 512
#define NC 256
#define NAR 1024
#define NH 256
#define NK 32
#define NSTEPS 64

// ---------------- static device scratch ----------------
__device__ float g_keyproj[(size_t)NB * NE * NK];   // 16 MB
__device__ float g_xpart[8 * NB * NH];              // split-K partials of ar0@W1
__device__ float g_WpW1[NK * NH];                   // Wp@W1 (32x256)
__device__ float g_bpW1[NH];                        // bp@W1
__device__ uint2 g_subkeys[NSTEPS];
__device__ int   g_action[NB];

#define OFF_UNITS ((size_t)NB * NSTEPS * NE)
#define OFF_AR    (OFF_UNITS + (size_t)NB * NSTEPS)

// ---------------- Threefry-2x32 (20 rounds) ----------------
__device__ __forceinline__ void tf2x32(uint32_t k0, uint32_t k1,
                                       uint32_t x0, uint32_t x1,
                                       uint32_t &o0, uint32_t &o1) {
  uint32_t ks2 = k0 ^ k1 ^ 0x1BD11BDAu;
  x0 += k0; x1 += k1;
#define RND(r) { x0 += x1; x1 = __funnelshift_l(x1, x1, (r)); x1 ^= x0; }
  RND(13) RND(15) RND(26) RND(6)   x0 += k1;  x1 += ks2 + 1u;
  RND(17) RND(29) RND(16) RND(24)  x0 += ks2; x1 += k0  + 2u;
  RND(13) RND(15) RND(26) RND(6)   x0 += k0;  x1 += k1  + 3u;
  RND(17) RND(29) RND(16) RND(24)  x0 += k1;  x1 += ks2 + 4u;
  RND(13) RND(15) RND(26) RND(6)   x0 += ks2; x1 += k0  + 5u;
#undef RND
  o0 = x0; o1 = x1;
}

__device__ __forceinline__ float gumbelize(uint32_t bits) {
  float f = __uint_as_float((bits >> 9) | 0x3f800000u) - 1.0f;
  f = fmaxf(f, 1e-20f);
  return -logf(-logf(f));
}

__device__ __forceinline__ unsigned fenc(float f) {
  unsigned u = __float_as_uint(f);
  return (u & 0x80000000u) ? ~u : (u | 0x80000000u);
}

// ---------------- setup ----------------
__global__ void setup_kernel(const int* __restrict__ action_raw) {
  bool is64 = true;
  for (int i = 1; i < 256; i += 2)
    if (action_raw[i] != 0) { is64 = false; break; }
  for (int b = 0; b < NB; b++)
    g_action[b] = is64 ? action_raw[2 * b] : action_raw[b];

  uint32_t k0 = 0u, k1 = 42u;
  for (int s = 0; s < NSTEPS; s++) {
    uint32_t n0, n1, s0, s1;
    tf2x32(k0, k1, 0u, 0u, n0, n1);
    tf2x32(k0, k1, 0u, 1u, s0, s1);
    g_subkeys[s] = make_uint2(s0, s1);
    k0 = n0; k1 = n1;
  }
}

// ---------------- WpW1 = Wp@W1, bpW1 = bp@W1 ----------------
__global__ void wpw1_kernel(const float* __restrict__ Wp, const float* __restrict__ bp,
                            const float* __restrict__ W1) {
  __shared__ float s_row[NAR];
  int i = blockIdx.x, t = threadIdx.x;
  for (int k = t; k < NAR; k += 256)
    s_row[k] = (i < NK) ? Wp[(size_t)i * NAR + k] : bp[k];
  __syncthreads();
  float a0 = 0.f, a1 = 0.f, a2 = 0.f, a3 = 0.f;
  for (int k = 0; k < NAR; k += 4) {
    a0 += s_row[k]     * W1[(size_t)k * NH + t];
    a1 += s_row[k + 1] * W1[(size_t)(k + 1) * NH + t];
    a2 += s_row[k + 2] * W1[(size_t)(k + 2) * NH + t];
    a3 += s_row[k + 3] * W1[(size_t)(k + 3) * NH + t];
  }
  float acc = (a0 + a1) + (a2 + a3);
  if (i < NK) g_WpW1[i * NH + t] = acc; else g_bpW1[t] = acc;
}

// ---------------- split-K GEMM: xpart[z] = ar0[:, z*128:(z+1)*128] @ W1 slice ----------------
#define BM 32
#define BN 64
#define BK 16
#define KSL 128
__global__ void gemm_kernel(const float* __restrict__ ar0, const float* __restrict__ W1) {
  __shared__ __align__(16) float As[BK][BM + 1];
  __shared__ __align__(16) float Bs[BK][68];
  int bm = blockIdx.y * BM, bn = blockIdx.x * BN, k0 = blockIdx.z * KSL;
  int t = threadIdx.x;
  int ty = t >> 4, tx = t & 15;
  float acc[2][4] = {{0.f,0.f,0.f,0.f},{0.f,0.f,0.f,0.f}};

  for (int kc = 0; kc < KSL; kc += BK) {
    {
      int m = t >> 3;
      int kk = (t & 7) * 2;
      const float* p = ar0 + (size_t)(bm + m) * NAR + (k0 + kc + kk);
      As[kk][m] = p[0];
      As[kk + 1][m] = p[1];
    }
    {
      int kk = t >> 4;
      int j = (t & 15) * 4;
      const float* p = W1 + (size_t)(k0 + kc + kk) * NH + bn + j;
      Bs[kk][j] = p[0]; Bs[kk][j+1] = p[1]; Bs[kk][j+2] = p[2]; Bs[kk][j+3] = p[3];
    }
    __syncthreads();
    #pragma unroll
    for (int k = 0; k < BK; k++) {
      float a0 = As[k][ty * 2], a1 = As[k][ty * 2 + 1];
      float4 bv = *reinterpret_cast<const float4*>(&Bs[k][tx * 4]);
      acc[0][0] += a0 * bv.x; acc[0][1] += a0 * bv.y; acc[0][2] += a0 * bv.z; acc[0][3] += a0 * bv.w;
      acc[1][0] += a1 * bv.x; acc[1][1] += a1 * bv.y; acc[1][2] += a1 * bv.z; acc[1][3] += a1 * bv.w;
    }
    __syncthreads();
  }
  float* xp = g_xpart + (size_t)blockIdx.z * (NB * NH);
  #pragma unroll
  for (int im = 0; im < 2; im++) {
    int row = bm + ty * 2 + im;
    float* o = xp + (size_t)row * NH + bn + tx * 4;
    o[0] = acc[im][0]; o[1] = acc[im][1]; o[2] = acc[im][2]; o[3] = acc[im][3];
  }
}

// ---------------- persistent per-batch kernel ----------------
// smem layout (floats):
// [0, 24576): persistent weights (prologue aliases this as scratch)
//   WpW1 8192 | W2 8192 | Wx 4096 | Wh 4096
// scratch alias: s_wk 8192 | s_emb 32*260=8320
// tail at 24576: see offsets below. total floats 24576+2400.
#define SMEM_FLOATS (24576 + 2400)

__global__ __launch_bounds__(256, 2) void persist_kernel(
    const float* __restrict__ ar0, const float* __restrict__ emb,
    const float* __restrict__ Wf, const float* __restrict__ bf,
    const float* __restrict__ Wk, const float* __restrict__ bk,
    const float* __restrict__ W1, const float* __restrict__ b1,
    const float* __restrict__ W2, const float* __restrict__ b2,
    const float* __restrict__ Wx, const float* __restrict__ Wh,
    const float* __restrict__ bl, const float* __restrict__ Wp,
    const float* __restrict__ bp, const float* __restrict__ table,
    const float* __restrict__ selt, float* __restrict__ out)
{
  extern __shared__ float sm[];
  float* s_WpW1 = sm;
  float* s_W2   = sm + 8192;
  float* s_Wx   = sm + 16384;
  float* s_Wh   = sm + 20480;
  float* tail   = sm + 24576;
  float* s_func = tail;
  float* s_x    = tail + 256;
  float* s_bpW1 = tail + 512;
  float* s_bl   = tail + 768;
  float* s_b2   = tail + 896;
  float* s_mask = tail + 928;    // 512
  float* s_h    = tail + 1440;
  float* s_c    = tail + 1472;
  float* s_z2   = tail + 1504;
  float* s_o32  = tail + 1536;
  float* s_sum  = tail + 1568;
  float* s_t    = tail + 1600;   // 256
  float* s_red  = tail + 1856;   // 256
  float* s_zb   = tail + 2112;   // 256
  unsigned long long* s_key = (unsigned long long*)(tail + 2368);  // 8
  int* s_id = (int*)(tail + 2384);
  // prologue scratch aliases
  float* s_wk  = sm;             // 8192
  float* s_emb = sm + 8192;      // 8320

  int b = blockIdx.x, t = threadIdx.x;
  int lane = t & 31, wid = t >> 5;

  int a_act = g_action[b];
  float sel = selt[a_act];

  // ======== prologue: keyproj[b] = emb[b] @ Wk + bk ========
  for (int i = t; i < NC * NK; i += 256) s_wk[i] = Wk[i];
  __syncthreads();
  {
    float bkv = bk[lane];
    const float* embB = emb + (size_t)b * NE * NC;
    for (int pass = 0; pass < 16; pass++) {
      // stage 32 rows x 256 cols, padded stride 260
      for (int i = t * 4; i < 32 * 256; i += 1024) {
        int r = i >> 8, c = i & 255;
        float4 v = *(const float4*)(embB + (size_t)(pass * 32 + r) * NC + c);
        float* d = s_emb + r * 260 + c;
        d[0] = v.x; d[1] = v.y; d[2] = v.z; d[3] = v.w;
      }
      __syncthreads();
      float acc0 = bkv, acc1 = bkv, acc2 = bkv, acc3 = bkv;
      const float* eb = s_emb + (wid * 4) * 260;
      #pragma unroll 8
      for (int c = 0; c < NC; c += 4) {
        float w0 = s_wk[(c + 0) * 32 + lane];
        float w1 = s_wk[(c + 1) * 32 + lane];
        float w2 = s_wk[(c + 2) * 32 + lane];
        float w3 = s_wk[(c + 3) * 32 + lane];
        float4 a0 = *(const float4*)(eb + c);
        float4 a1 = *(const float4*)(eb + 260 + c);
        float4 a2 = *(const float4*)(eb + 520 + c);
        float4 a3 = *(const float4*)(eb + 780 + c);
        acc0 += a0.x * w0 + a0.y * w1 + a0.z * w2 + a0.w * w3;
        acc1 += a1.x * w0 + a1.y * w1 + a1.z * w2 + a1.w * w3;
        acc2 += a2.x * w0 + a2.y * w1 + a2.z * w2 + a2.w * w3;
        acc3 += a3.x * w0 + a3.y * w1 + a3.z * w2 + a3.w * w3;
      }
      float* kp = g_keyproj + ((size_t)(b * NE) + pass * 32 + wid * 4) * NK + lane;
      kp[0] = acc0; kp[32] = acc1; kp[64] = acc2; kp[96] = acc3;
      __syncthreads();
    }
  }

  // ======== prologue: func embed ========
  for (int i = t; i < 256; i += 256) s_emb[i] = table[(size_t)a_act * 256 + i];
  __syncthreads();
  {
    float a0 = 0.f, a1 = 0.f;
    #pragma unroll 4
    for (int k = 0; k < 256; k += 2) {
      a0 += s_emb[k]     * Wf[(size_t)k * 256 + t];
      a1 += s_emb[k + 1] * Wf[(size_t)(k + 1) * 256 + t];
    }
    s_func[t] = fmaxf(bf[t] + a0 + a1, 0.0f);
  }
  __syncthreads();

  // ======== prologue: x0 = sum of split-K partials + b1 ========
  {
    float xv = b1[t];
    #pragma unroll
    for (int p = 0; p < 8; p++) xv += g_xpart[p * (NB * NH) + b * NH + t];
    s_x[t] = xv;
  }
  __syncthreads();   // done with scratch; load persistent weights

  for (int i = t; i < 8192; i += 256) s_WpW1[i] = g_WpW1[i & 8191];
  for (int i = t; i < 8192; i += 256) s_W2[i] = W2[i];
  for (int i = t; i < 4096; i += 256) { s_Wx[i] = Wx[i]; s_Wh[i] = Wh[i]; }
  s_bpW1[t] = g_bpW1[t & 255];
  if (t < 128) s_bl[t] = bl[t];
  if (t < 32) { s_b2[t] = b2[t]; s_h[t] = 0.f; s_c[t] = 0.f; s_sum[t] = 0.f; s_o32[t] = 0.f; }
  s_mask[t] = 1.0f; s_mask[t + 256] = 1.0f;
  __syncthreads();

  // ======== 64-step loop ========
  for (int s = 0; s < NSTEPS; s++) {
    // x update via precomputed WpW1
    if (s > 0) {
      float xv = s_x[t] + s_bpW1[t];
      #pragma unroll
      for (int k = 0; k < 32; k++) xv += s_o32[k] * s_WpW1[k * 256 + t];
      s_x[t] = xv;
    }
    s_t[t] = fmaxf(s_func[t] + s_x[t], 0.0f);
    __syncthreads();

    // z2 = relu(...) @ W2 + b2  (8 partial groups)
    {
      float acc = 0.f;
      const float* ww = s_W2 + (size_t)(wid * 32) * 32 + lane;
      const float* st = s_t + wid * 32;
      #pragma unroll
      for (int j = 0; j < 32; j++) acc += st[j] * ww[j * 32];
      s_red[t] = acc;
    }
    __syncthreads();
    if (t < 32) {
      float z2 = s_b2[t];
      #pragma unroll
      for (int p = 0; p < 8; p++) z2 += s_red[p * 32 + t];
      s_z2[t] = z2;
    }
    __syncthreads();

    // LSTM preactivations (two halves: Wx part, Wh part)
    {
      int u = t & 127;
      const float* wm = (t < 128) ? s_Wx : s_Wh;
      const float* vv = (t < 128) ? s_z2 : s_h;
      float acc = (t < 128) ? s_bl[u] : 0.f;
      #pragma unroll
      for (int k = 0; k < 32; k++) acc += vv[k] * wm[k * 128 + u];
      s_zb[t] = acc;
    }
    __syncthreads();
    if (t < 32) {
      float zi = s_zb[t]      + s_zb[128 + t];
      float zf = s_zb[32 + t] + s_zb[160 + t];
      float zg = s_zb[64 + t] + s_zb[192 + t];
      float zo = s_zb[96 + t] + s_zb[224 + t];
      float iv = 1.f / (1.f + expf(-zi));
      float fv = 1.f / (1.f + expf(-zf));
      float gv = tanhf(zg);
      float ov = 1.f / (1.f + expf(-zo));
      float cv = fv * s_c[t] + iv * gv;
      float hv = ov * tanhf(cv);
      s_c[t] = cv; s_h[t] = hv;
    }
    __syncthreads();

    // attention: y = keyproj . h, masked; write logits
    float y2a[2];
    float vmax = -3.0e38f;
    #pragma unroll
    for (int r = 0; r < 2; r++) {
      int e = t + r * 256;
      const float4* kr = (const float4*)(g_keyproj + ((size_t)(b * NE + e)) * NK);
      float acc = 0.f;
      #pragma unroll
      for (int q = 0; q < 8; q++) {
        float4 v = kr[q];
        acc += v.x * s_h[4*q] + v.y * s_h[4*q+1] + v.z * s_h[4*q+2] + v.w * s_h[4*q+3];
      }
      float y2 = acc * s_mask[e];
      out[((size_t)b * NSTEPS + s) * NE + e] = y2 * sel;
      y2a[r] = y2;
      vmax = fmaxf(vmax, y2);
    }
    // max reduce
    #pragma unroll
    for (int o = 16; o; o >>= 1) vmax = fmaxf(vmax, __shfl_xor_sync(0xffffffffu, vmax, o));
    if (lane == 0) s_red[wid] = vmax;
    __syncthreads();
    if (t == 0) {
      float m = s_red[0];
      #pragma unroll
      for (int i = 1; i < 8; i++) m = fmaxf(m, s_red[i]);
      s_red[32] = m;
    }
    __syncthreads();
    float mx = s_red[32];
    float p0 = expf(y2a[0] - mx), p1 = expf(y2a[1] - mx);
    // sum reduce
    float ssum = p0 + p1;
    #pragma unroll
    for (int o = 16; o; o >>= 1) ssum += __shfl_xor_sync(0xffffffffu, ssum, o);
    if (lane == 0) s_red[64 + wid] = ssum;
    __syncthreads();
    if (t == 0) {
      float m = 0.f;
      #pragma unroll
      for (int i = 0; i < 8; i++) m += s_red[64 + i];
      s_red[33] = m;
    }
    __syncthreads();
    float smv = s_red[33];

    // gumbel (inline threefry) + argmax
    uint2 sk = g_subkeys[s];
    uint32_t o0, o1;
    tf2x32(sk.x, sk.y, 0u, (uint32_t)(b * 512 + t), o0, o1);
    float v0 = p0 / smv + gumbelize(o0 ^ o1);
    tf2x32(sk.x, sk.y, 0u, (uint32_t)(b * 512 + t + 256), o0, o1);
    float v1 = p1 / smv + gumbelize(o0 ^ o1);
    unsigned long long kA = ((unsigned long long)fenc(v0) << 32) | (unsigned long long)(0xFFFFFFFFu - (unsigned)t);
    unsigned long long kB = ((unsigned long long)fenc(v1) << 32) | (unsigned long long)(0xFFFFFFFFu - (unsigned)(t + 256));
    unsigned long long km = (kA > kB) ? kA : kB;
    #pragma unroll
    for (int o = 16; o; o >>= 1) {
      unsigned long long other = __shfl_xor_sync(0xffffffffu, km, o);
      if (other > km) km = other;
    }
    if (lane == 0) s_key[wid] = km;
    __syncthreads();
    if (t == 0) {
      unsigned long long m = s_key[0];
      #pragma unroll
      for (int i = 1; i < 8; i++) if (s_key[i] > m) m = s_key[i];
      int id = (int)(0xFFFFFFFFu - (unsigned)(m & 0xFFFFFFFFull));
      s_id[0] = id;
      s_mask[id] = 0.0f;
      out[OFF_UNITS + (size_t)b * NSTEPS + s] = (float)id * sel;
    }
    __syncthreads();
    int id = s_id[0];
    if (t < 32) {
      float ov = g_keyproj[((size_t)(b * NE + id)) * NK + t] - 0.001953125f;  // -1/512
      s_o32[t] = ov;
      s_sum[t] += ov;
    }
    __syncthreads();
  }

  // ======== epilogue: ar_out = (ar0 + sum@Wp + 64*bp) * sel ========
  for (int j = t; j < NAR; j += 256) {
    float acc = ar0[(size_t)b * NAR + j] + 64.0f * bp[j];
    #pragma unroll
    for (int k = 0; k < 32; k++) acc += s_sum[k] * Wp[(size_t)k * NAR + j];
    out[OFF_AR + (size_t)b * NAR + j] = acc * sel;
  }
}

// ---------------- launcher ----------------
extern "C" void kernel_launch(void* const* d_in, const int* in_sizes, int n_in,
                              void* d_out, int out_size) {
  const float* ar_in   = (const float*)d_in[0];
  const int*   action  = (const int*)  d_in[1];
  const float* emb     = (const float*)d_in[2];
  const float* Wf      = (const float*)d_in[3];
  const float* bf      = (const float*)d_in[4];
  const float* Wk      = (const float*)d_in[5];
  const float* bk      = (const float*)d_in[6];
  const float* W1      = (const float*)d_in[7];
  const float* b1      = (const float*)d_in[8];
  const float* W2      = (const float*)d_in[9];
  const float* b2      = (const float*)d_in[10];
  const float* Wx      = (const float*)d_in[11];
  const float* Wh      = (const float*)d_in[12];
  const float* bl      = (const float*)d_in[13];
  const float* Wp      = (const float*)d_in[14];
  const float* bp      = (const float*)d_in[15];
  const float* table   = (const float*)d_in[16];
  const float* selt    = (const float*)d_in[17];
  float* out = (float*)d_out;

  static int cfg_done = 0;
  cudaFuncSetAttribute(persist_kernel, cudaFuncAttributeMaxDynamicSharedMemorySize,
                       SMEM_FLOATS * (int)sizeof(float));
  (void)cfg_done;

  setup_kernel<<<1, 1>>>(action);
  wpw1_kernel<<<33, 256>>>(Wp, bp, W1);
  gemm_kernel<<<dim3(4, 8, 8), 256>>>(ar_in, W1);
  persist_kernel<<<256, 256, SMEM_FLOATS * sizeof(float)>>>(
      ar_in, emb, Wf, bf, Wk, bk, W1, b1, W2, b2, Wx, Wh, bl, Wp, bp, table, selt, out);
}

// round 4
// speedup vs baseline: 4.0384x; 1.6220x over previous
#include <cuda_runtime.h>
#include <stdint.h>

#define NB 256
#define NE 512
#define NC 256
#define NAR 1024
#define NH 256
#define NK 32
#define NSTEPS 64

// ---------------- static device scratch ----------------
__device__ float g_xpart[8 * NB * NH];
__device__ float g_WpW1[NK * NH];
__device__ float g_bpW1[NH];
__device__ uint2 g_subkeys[NSTEPS];
__device__ int   g_action[NB];

#define OFF_UNITS ((size_t)NB * NSTEPS * NE)
#define OFF_AR    (OFF_UNITS + (size_t)NB * NSTEPS)

// ---------------- Threefry-2x32 (20 rounds) ----------------
__device__ __forceinline__ void tf2x32(uint32_t k0, uint32_t k1,
                                       uint32_t x0, uint32_t x1,
                                       uint32_t &o0, uint32_t &o1) {
  uint32_t ks2 = k0 ^ k1 ^ 0x1BD11BDAu;
  x0 += k0; x1 += k1;
#define RND(r) { x0 += x1; x1 = __funnelshift_l(x1, x1, (r)); x1 ^= x0; }
  RND(13) RND(15) RND(26) RND(6)   x0 += k1;  x1 += ks2 + 1u;
  RND(17) RND(29) RND(16) RND(24)  x0 += ks2; x1 += k0  + 2u;
  RND(13) RND(15) RND(26) RND(6)   x0 += k0;  x1 += k1  + 3u;
  RND(17) RND(29) RND(16) RND(24)  x0 += k1;  x1 += ks2 + 4u;
  RND(13) RND(15) RND(26) RND(6)   x0 += ks2; x1 += k0  + 5u;
#undef RND
  o0 = x0; o1 = x1;
}

__device__ __forceinline__ float gumbelize(uint32_t bits) {
  float f = __uint_as_float((bits >> 9) | 0x3f800000u) - 1.0f;
  f = fmaxf(f, 1e-20f);
  return -logf(-logf(f));
}

__device__ __forceinline__ unsigned fenc(float f) {
  unsigned u = __float_as_uint(f);
  return (u & 0x80000000u) ? ~u : (u | 0x80000000u);
}

// ---------------- setup ----------------
__global__ void setup_kernel(const int* __restrict__ action_raw) {
  bool is64 = true;
  for (int i = 1; i < 256; i += 2)
    if (action_raw[i] != 0) { is64 = false; break; }
  for (int b = 0; b < NB; b++)
    g_action[b] = is64 ? action_raw[2 * b] : action_raw[b];

  uint32_t k0 = 0u, k1 = 42u;
  for (int s = 0; s < NSTEPS; s++) {
    uint32_t n0, n1, s0, s1;
    tf2x32(k0, k1, 0u, 0u, n0, n1);
    tf2x32(k0, k1, 0u, 1u, s0, s1);
    g_subkeys[s] = make_uint2(s0, s1);
    k0 = n0; k1 = n1;
  }
}

// ---------------- WpW1 = Wp@W1, bpW1 = bp@W1 ----------------
__global__ void wpw1_kernel(const float* __restrict__ Wp, const float* __restrict__ bp,
                            const float* __restrict__ W1) {
  __shared__ float s_row[NAR];
  int i = blockIdx.x, t = threadIdx.x;
  for (int k = t; k < NAR; k += 256)
    s_row[k] = (i < NK) ? Wp[(size_t)i * NAR + k] : bp[k];
  __syncthreads();
  float a0 = 0.f, a1 = 0.f, a2 = 0.f, a3 = 0.f;
  for (int k = 0; k < NAR; k += 4) {
    a0 += s_row[k]     * W1[(size_t)k * NH + t];
    a1 += s_row[k + 1] * W1[(size_t)(k + 1) * NH + t];
    a2 += s_row[k + 2] * W1[(size_t)(k + 2) * NH + t];
    a3 += s_row[k + 3] * W1[(size_t)(k + 3) * NH + t];
  }
  float acc = (a0 + a1) + (a2 + a3);
  if (i < NK) g_WpW1[i * NH + t] = acc; else g_bpW1[t] = acc;
}

// ---------------- split-K GEMM: xpart[z] = ar0 slice @ W1 slice ----------------
#define BM 32
#define BN 64
#define BK 16
#define KSL 128
__global__ void gemm_kernel(const float* __restrict__ ar0, const float* __restrict__ W1) {
  __shared__ __align__(16) float As[BK][BM + 1];
  __shared__ __align__(16) float Bs[BK][68];
  int bm = blockIdx.y * BM, bn = blockIdx.x * BN, k0 = blockIdx.z * KSL;
  int t = threadIdx.x;
  int ty = t >> 4, tx = t & 15;
  float acc[2][4] = {{0.f,0.f,0.f,0.f},{0.f,0.f,0.f,0.f}};

  for (int kc = 0; kc < KSL; kc += BK) {
    {
      int m = t >> 3;
      int kk = (t & 7) * 2;
      const float* p = ar0 + (size_t)(bm + m) * NAR + (k0 + kc + kk);
      As[kk][m] = p[0];
      As[kk + 1][m] = p[1];
    }
    {
      int kk = t >> 4;
      int j = (t & 15) * 4;
      const float* p = W1 + (size_t)(k0 + kc + kk) * NH + bn + j;
      Bs[kk][j] = p[0]; Bs[kk][j+1] = p[1]; Bs[kk][j+2] = p[2]; Bs[kk][j+3] = p[3];
    }
    __syncthreads();
    #pragma unroll
    for (int k = 0; k < BK; k++) {
      float a0 = As[k][ty * 2], a1 = As[k][ty * 2 + 1];
      float4 bv = *reinterpret_cast<const float4*>(&Bs[k][tx * 4]);
      acc[0][0] += a0 * bv.x; acc[0][1] += a0 * bv.y; acc[0][2] += a0 * bv.z; acc[0][3] += a0 * bv.w;
      acc[1][0] += a1 * bv.x; acc[1][1] += a1 * bv.y; acc[1][2] += a1 * bv.z; acc[1][3] += a1 * bv.w;
    }
    __syncthreads();
  }
  float* xp = g_xpart + (size_t)blockIdx.z * (NB * NH);
  #pragma unroll
  for (int im = 0; im < 2; im++) {
    int row = bm + ty * 2 + im;
    float* o = xp + (size_t)row * NH + bn + tx * 4;
    o[0] = acc[im][0]; o[1] = acc[im][1]; o[2] = acc[im][2]; o[3] = acc[im][3];
  }
}

// ---------------- persistent per-batch kernel ----------------
#define KPS 36
#define OFF_KP   0          // 512*36 = 18432
#define OFF_WX   18432      // 4096
#define OFF_WH   22528      // 4096
#define OFF_T    26624      // 256
#define OFF_ZR   26880      // 256
#define OFF_RED  27136      // 32 (0-7 max, 8-15 sum)
#define OFF_MASK 27168      // 512
#define OFF_H    27680      // 32
#define OFF_O32  27712      // 32
#define OFF_SUM  27744      // 32
#define OFF_G    27776      // 64 (warp0 gumbels, filled by warp1)
#define OFF_KEY  27840      // 16 fl (8 u64)
#define OFF_ID   27856
#define SMEM_FLOATS 27872

__global__ __launch_bounds__(256, 2) void persist_kernel(
    const float* __restrict__ ar0, const float* __restrict__ emb,
    const float* __restrict__ Wf, const float* __restrict__ bf,
    const float* __restrict__ Wk, const float* __restrict__ bk,
    const float* __restrict__ W1, const float* __restrict__ b1,
    const float* __restrict__ W2, const float* __restrict__ b2,
    const float* __restrict__ Wx, const float* __restrict__ Wh,
    const float* __restrict__ bl, const float* __restrict__ Wp,
    const float* __restrict__ bp, const float* __restrict__ table,
    const float* __restrict__ selt, float* __restrict__ out)
{
  extern __shared__ float sm[];
  float* s_kp   = sm + OFF_KP;
  float* s_Wx   = sm + OFF_WX;
  float* s_Wh   = sm + OFF_WH;
  float* s_t    = sm + OFF_T;
  float* s_zred = sm + OFF_ZR;
  float* s_red  = sm + OFF_RED;
  float* s_mask = sm + OFF_MASK;
  float* s_h    = sm + OFF_H;
  float* s_o32  = sm + OFF_O32;
  float* s_sum  = sm + OFF_SUM;
  float* s_g    = sm + OFF_G;
  unsigned long long* s_key = (unsigned long long*)(sm + OFF_KEY);
  int* s_id = (int*)(sm + OFF_ID);
  float* s_wk = sm + OFF_WX;   // prologue alias (8192 fl over Wx+Wh)

  int b = blockIdx.x, t = threadIdx.x;
  int lane = t & 31, wid = t >> 5;

  int a_act = g_action[b];
  float sel = selt[a_act];

  // ======== prologue A: keyproj[b] into smem ========
  for (int i = t; i < NC * NK; i += 256) s_wk[i] = Wk[i];
  __syncthreads();
  {
    float bkv = bk[lane];
    const float* embB = emb + (size_t)b * NE * NC;
    for (int pass = 0; pass < 16; pass++) {
      int r = pass * 32 + wid * 4;
      const float* e0p = embB + (size_t)r * NC + lane;
      float a0 = bkv, a1 = bkv, a2 = bkv, a3 = bkv;
      float e0 = e0p[0], e1 = e0p[256], e2 = e0p[512], e3 = e0p[768];
      #pragma unroll
      for (int j = 0; j < 8; j++) {
        float n0 = 0.f, n1 = 0.f, n2 = 0.f, n3 = 0.f;
        if (j < 7) {
          const float* np = e0p + (j + 1) * 32;
          n0 = np[0]; n1 = np[256]; n2 = np[512]; n3 = np[768];
        }
        const float* wkc = s_wk + (j * 32) * 32 + lane;
        #pragma unroll
        for (int cc = 0; cc < 32; cc++) {
          float w = wkc[cc * 32];
          a0 = fmaf(__shfl_sync(0xffffffffu, e0, cc), w, a0);
          a1 = fmaf(__shfl_sync(0xffffffffu, e1, cc), w, a1);
          a2 = fmaf(__shfl_sync(0xffffffffu, e2, cc), w, a2);
          a3 = fmaf(__shfl_sync(0xffffffffu, e3, cc), w, a3);
        }
        e0 = n0; e1 = n1; e2 = n2; e3 = n3;
      }
      s_kp[(r + 0) * KPS + lane] = a0;
      s_kp[(r + 1) * KPS + lane] = a1;
      s_kp[(r + 2) * KPS + lane] = a2;
      s_kp[(r + 3) * KPS + lane] = a3;
    }
  }
  __syncthreads();

  // ======== prologue B: stage table row; load Wx/Wh (overwrites wk); mask init ========
  s_t[t] = table[(size_t)a_act * 256 + t];
  for (int i = t; i < 4096; i += 256) { s_Wx[i] = Wx[i]; s_Wh[i] = Wh[i]; }
  s_mask[t] = 1.0f; s_mask[t + 256] = 1.0f;
  __syncthreads();

  // ======== prologue C: func embed, x0, register weights ========
  float func_r;
  {
    float a0 = 0.f, a1 = 0.f;
    #pragma unroll 4
    for (int k = 0; k < 256; k += 2) {
      a0 = fmaf(s_t[k],     Wf[(size_t)k * 256 + t], a0);
      a1 = fmaf(s_t[k + 1], Wf[(size_t)(k + 1) * 256 + t], a1);
    }
    func_r = fmaxf(bf[t] + a0 + a1, 0.0f);
  }
  float x_r = b1[t];
  #pragma unroll
  for (int p = 0; p < 8; p++) x_r += g_xpart[p * (NB * NH) + b * NH + t];

  float wpw1r[32], w2r[32];
  #pragma unroll
  for (int k = 0; k < 32; k++) wpw1r[k] = g_WpW1[k * NH + t];
  #pragma unroll
  for (int j = 0; j < 32; j++) w2r[j] = W2[(size_t)(wid * 32 + j) * 32 + lane];
  float bpw1r = g_bpW1[t];

  float hreg = 0.f, creg = 0.f, sumr = 0.f;
  float blr0 = 0.f, blr1 = 0.f, blr2 = 0.f, blr3 = 0.f, b2r = 0.f;
  if (wid == 0) {
    blr0 = bl[lane]; blr1 = bl[32 + lane]; blr2 = bl[64 + lane]; blr3 = bl[96 + lane];
    b2r = b2[lane];
  }
  __syncthreads();

  // ======== 64-step loop ========
  for (int s = 0; s < NSTEPS; s++) {
    // A: x update + relu
    if (s > 0) {
      float xv = x_r + bpw1r;
      #pragma unroll
      for (int k = 0; k < 32; k++) xv = fmaf(s_o32[k], wpw1r[k], xv);
      x_r = xv;
    }
    s_t[t] = fmaxf(func_r + x_r, 0.0f);
    __syncthreads();

    // B: z2 partials
    {
      float acc = 0.f;
      const float* st = s_t + wid * 32;
      #pragma unroll
      for (int j = 0; j < 32; j++) acc = fmaf(st[j], w2r[j], acc);
      s_zred[t] = acc;
    }
    __syncthreads();

    // C: warp0 = z2 reduce + LSTM + gates; warps1-7 = gumbel
    float g0 = 0.f, g1 = 0.f;
    uint2 sk = g_subkeys[s];
    if (wid == 0) {
      float z2 = b2r;
      #pragma unroll
      for (int p = 0; p < 8; p++) z2 += s_zred[p * 32 + lane];
      float zi = blr0, zf = blr1, zg = blr2, zo = blr3;
      #pragma unroll
      for (int k = 0; k < 32; k++) {
        float z2k = __shfl_sync(0xffffffffu, z2, k);
        float hk  = __shfl_sync(0xffffffffu, hreg, k);
        zi = fmaf(z2k, s_Wx[k * 128 + lane],      fmaf(hk, s_Wh[k * 128 + lane],      zi));
        zf = fmaf(z2k, s_Wx[k * 128 + 32 + lane], fmaf(hk, s_Wh[k * 128 + 32 + lane], zf));
        zg = fmaf(z2k, s_Wx[k * 128 + 64 + lane], fmaf(hk, s_Wh[k * 128 + 64 + lane], zg));
        zo = fmaf(z2k, s_Wx[k * 128 + 96 + lane], fmaf(hk, s_Wh[k * 128 + 96 + lane], zo));
      }
      float iv = 1.f / (1.f + expf(-zi));
      float fv = 1.f / (1.f + expf(-zf));
      float gv = tanhf(zg);
      float ov = 1.f / (1.f + expf(-zo));
      creg = fv * creg + iv * gv;
      hreg = ov * tanhf(creg);
      s_h[lane] = hreg;
    } else {
      uint32_t o0, o1;
      tf2x32(sk.x, sk.y, 0u, (uint32_t)(b * 512 + t), o0, o1);
      g0 = gumbelize(o0 ^ o1);
      tf2x32(sk.x, sk.y, 0u, (uint32_t)(b * 512 + t + 256), o0, o1);
      g1 = gumbelize(o0 ^ o1);
      if (wid == 1) {   // cover warp0's gumbels
        uint32_t p0b, p1b;
        tf2x32(sk.x, sk.y, 0u, (uint32_t)(b * 512 + lane), p0b, p1b);
        s_g[lane] = gumbelize(p0b ^ p1b);
        tf2x32(sk.x, sk.y, 0u, (uint32_t)(b * 512 + lane + 256), p0b, p1b);
        s_g[32 + lane] = gumbelize(p0b ^ p1b);
      }
    }
    __syncthreads();
    if (wid == 0) { g0 = s_g[lane]; g1 = s_g[32 + lane]; }

    // D: attention dots + logits store + warp max
    float4 h4[8];
    #pragma unroll
    for (int q = 0; q < 8; q++) h4[q] = *(const float4*)(s_h + 4 * q);
    float y0, y1;
    {
      const float4* kr = (const float4*)(s_kp + (size_t)t * KPS);
      float acc = 0.f;
      #pragma unroll
      for (int q = 0; q < 8; q++) {
        float4 v = kr[q];
        acc += v.x * h4[q].x + v.y * h4[q].y + v.z * h4[q].z + v.w * h4[q].w;
      }
      y0 = acc * s_mask[t];
    }
    {
      const float4* kr = (const float4*)(s_kp + (size_t)(t + 256) * KPS);
      float acc = 0.f;
      #pragma unroll
      for (int q = 0; q < 8; q++) {
        float4 v = kr[q];
        acc += v.x * h4[q].x + v.y * h4[q].y + v.z * h4[q].z + v.w * h4[q].w;
      }
      y1 = acc * s_mask[t + 256];
    }
    out[((size_t)b * NSTEPS + s) * NE + t] = y0 * sel;
    out[((size_t)b * NSTEPS + s) * NE + t + 256] = y1 * sel;
    float vmax = fmaxf(y0, y1);
    #pragma unroll
    for (int o = 16; o; o >>= 1) vmax = fmaxf(vmax, __shfl_xor_sync(0xffffffffu, vmax, o));
    if (lane == 0) s_red[wid] = vmax;
    __syncthreads();

    // E: exp + warp sum
    float mx = s_red[0];
    #pragma unroll
    for (int i = 1; i < 8; i++) mx = fmaxf(mx, s_red[i]);
    float p0 = expf(y0 - mx), p1 = expf(y1 - mx);
    float ssum = p0 + p1;
    #pragma unroll
    for (int o = 16; o; o >>= 1) ssum += __shfl_xor_sync(0xffffffffu, ssum, o);
    if (lane == 0) s_red[8 + wid] = ssum;
    __syncthreads();

    // F: argmax over p + S*g (same ordering as p/S + g)
    float S = s_red[8];
    #pragma unroll
    for (int i = 1; i < 8; i++) S += s_red[8 + i];
    float v0 = p0 + S * g0;
    float v1 = p1 + S * g1;
    unsigned long long kA = ((unsigned long long)fenc(v0) << 32) | (unsigned long long)(0xFFFFFFFFu - (unsigned)t);
    unsigned long long kB = ((unsigned long long)fenc(v1) << 32) | (unsigned long long)(0xFFFFFFFFu - (unsigned)(t + 256));
    unsigned long long km = (kA > kB) ? kA : kB;
    #pragma unroll
    for (int o = 16; o; o >>= 1) {
      unsigned long long other = __shfl_xor_sync(0xffffffffu, km, o);
      if (other > km) km = other;
    }
    if (lane == 0) s_key[wid] = km;
    __syncthreads();

    // G: warp0 finalizes id, mask, units, gather
    if (wid == 0) {
      unsigned long long kk = (lane < 8) ? s_key[lane] : 0ull;
      #pragma unroll
      for (int o = 4; o; o >>= 1) {
        unsigned long long other = __shfl_xor_sync(0xffffffffu, kk, o);
        if (other > kk) kk = other;
      }
      kk = __shfl_sync(0xffffffffu, kk, 0);
      int id = (int)(0xFFFFFFFFu - (unsigned)(kk & 0xFFFFFFFFull));
      float ov = s_kp[(size_t)id * KPS + lane] - 0.001953125f;  // -1/512
      s_o32[lane] = ov;
      sumr += ov;
      if (lane == 0) {
        s_mask[id] = 0.0f;
        out[OFF_UNITS + (size_t)b * NSTEPS + s] = (float)id * sel;
      }
    }
    __syncthreads();
  }

  // ======== epilogue ========
  if (wid == 0) s_sum[lane] = sumr;
  __syncthreads();
  for (int j = t; j < NAR; j += 256) {
    float acc = ar0[(size_t)b * NAR + j] + 64.0f * bp[j];
    #pragma unroll
    for (int k = 0; k < 32; k++) acc = fmaf(s_sum[k], Wp[(size_t)k * NAR + j], acc);
    out[OFF_AR + (size_t)b * NAR + j] = acc * sel;
  }
}

// ---------------- launcher ----------------
extern "C" void kernel_launch(void* const* d_in, const int* in_sizes, int n_in,
                              void* d_out, int out_size) {
  const float* ar_in   = (const float*)d_in[0];
  const int*   action  = (const int*)  d_in[1];
  const float* emb     = (const float*)d_in[2];
  const float* Wf      = (const float*)d_in[3];
  const float* bf      = (const float*)d_in[4];
  const float* Wk      = (const float*)d_in[5];
  const float* bk      = (const float*)d_in[6];
  const float* W1      = (const float*)d_in[7];
  const float* b1      = (const float*)d_in[8];
  const float* W2      = (const float*)d_in[9];
  const float* b2      = (const float*)d_in[10];
  const float* Wx      = (const float*)d_in[11];
  const float* Wh      = (const float*)d_in[12];
  const float* bl      = (const float*)d_in[13];
  const float* Wp      = (const float*)d_in[14];
  const float* bp      = (const float*)d_in[15];
  const float* table   = (const float*)d_in[16];
  const float* selt    = (const float*)d_in[17];
  float* out = (float*)d_out;

  cudaFuncSetAttribute(persist_kernel, cudaFuncAttributeMaxDynamicSharedMemorySize,
                       SMEM_FLOATS * (int)sizeof(float));

  setup_kernel<<<1, 1>>>(action);
  wpw1_kernel<<<33, 256>>>(Wp, bp, W1);
  gemm_kernel<<<dim3(4, 8, 8), 256>>>(ar_in, W1);
  persist_kernel<<<256, 256, SMEM_FLOATS * sizeof(float)>>>(
      ar_in, emb, Wf, bf, Wk, bk, W1, b1, W2, b2, Wx, Wh, bl, Wp, bp, table, selt, out);
}

// round 5
// speedup vs baseline: 4.6642x; 1.1550x over previous
#include <cuda_runtime.h>
#include <stdint.h>

#define NB 256
#define NE 512
#define NC 256
#define NAR 1024
#define NH 256
#define NK 32
#define NSTEPS 64

// ---------------- static device scratch ----------------
__device__ float g_xpart[8 * NB * NH];
__device__ float g_WpW1[NK * NH];
__device__ float g_bpW1[NH];
__device__ float g_gumbel[(size_t)NSTEPS * NB * NE];   // 32 MB
__device__ uint2 g_subkeys[NSTEPS];
__device__ int   g_action[NB];

#define OFF_UNITS ((size_t)NB * NSTEPS * NE)
#define OFF_AR    (OFF_UNITS + (size_t)NB * NSTEPS)

typedef unsigned long long ull;

// ---------------- f32x2 packed helpers ----------------
__device__ __forceinline__ void ffma2(ull &d, ull a, ull b) {
  asm("fma.rn.f32x2 %0, %1, %2, %3;" : "=l"(d) : "l"(a), "l"(b), "l"(d));
}
__device__ __forceinline__ ull dup2(float x) {
  ull r; asm("mov.b64 %0, {%1, %1};" : "=l"(r) : "f"(x)); return r;
}
__device__ __forceinline__ ull pack2(float x, float y) {
  ull r; asm("mov.b64 %0, {%1, %2};" : "=l"(r) : "f"(x), "f"(y)); return r;
}
__device__ __forceinline__ float2 unpack2(ull v) {
  float2 r; asm("mov.b64 {%0, %1}, %2;" : "=f"(r.x), "=f"(r.y) : "l"(v)); return r;
}

// ---------------- Threefry-2x32 (20 rounds) ----------------
__device__ __forceinline__ void tf2x32(uint32_t k0, uint32_t k1,
                                       uint32_t x0, uint32_t x1,
                                       uint32_t &o0, uint32_t &o1) {
  uint32_t ks2 = k0 ^ k1 ^ 0x1BD11BDAu;
  x0 += k0; x1 += k1;
#define RND(r) { x0 += x1; x1 = __funnelshift_l(x1, x1, (r)); x1 ^= x0; }
  RND(13) RND(15) RND(26) RND(6)   x0 += k1;  x1 += ks2 + 1u;
  RND(17) RND(29) RND(16) RND(24)  x0 += ks2; x1 += k0  + 2u;
  RND(13) RND(15) RND(26) RND(6)   x0 += k0;  x1 += k1  + 3u;
  RND(17) RND(29) RND(16) RND(24)  x0 += k1;  x1 += ks2 + 4u;
  RND(13) RND(15) RND(26) RND(6)   x0 += ks2; x1 += k0  + 5u;
#undef RND
  o0 = x0; o1 = x1;
}

__device__ __forceinline__ float gumbelize(uint32_t bits) {
  float f = __uint_as_float((bits >> 9) | 0x3f800000u) - 1.0f;
  f = fmaxf(f, 1e-20f);
  return -logf(-logf(f));
}

__device__ __forceinline__ unsigned fenc(float f) {
  unsigned u = __float_as_uint(f);
  return (u & 0x80000000u) ? ~u : (u | 0x80000000u);
}

// ---------------- setup ----------------
__global__ void setup_kernel(const int* __restrict__ action_raw) {
  bool is64 = true;
  for (int i = 1; i < 256; i += 2)
    if (action_raw[i] != 0) { is64 = false; break; }
  for (int b = 0; b < NB; b++)
    g_action[b] = is64 ? action_raw[2 * b] : action_raw[b];

  uint32_t k0 = 0u, k1 = 42u;
  for (int s = 0; s < NSTEPS; s++) {
    uint32_t n0, n1, s0, s1;
    tf2x32(k0, k1, 0u, 0u, n0, n1);
    tf2x32(k0, k1, 0u, 1u, s0, s1);
    g_subkeys[s] = make_uint2(s0, s1);
    k0 = n0; k1 = n1;
  }
}

// ---------------- gumbel table precompute ----------------
__global__ void gumbel_kernel() {
  int j = blockIdx.x * 256 + threadIdx.x;   // 0..131071 (= b*512 + e)
  int s = blockIdx.y;
  uint2 k = g_subkeys[s];
  uint32_t o0, o1;
  tf2x32(k.x, k.y, 0u, (uint32_t)j, o0, o1);
  g_gumbel[(size_t)s * (NB * NE) + j] = gumbelize(o0 ^ o1);
}

// ---------------- WpW1 = Wp@W1, bpW1 = bp@W1 ----------------
__global__ void wpw1_kernel(const float* __restrict__ Wp, const float* __restrict__ bp,
                            const float* __restrict__ W1) {
  __shared__ float s_row[NAR];
  int i = blockIdx.x, t = threadIdx.x;
  for (int k = t; k < NAR; k += 256)
    s_row[k] = (i < NK) ? Wp[(size_t)i * NAR + k] : bp[k];
  __syncthreads();
  float a0 = 0.f, a1 = 0.f, a2 = 0.f, a3 = 0.f;
  for (int k = 0; k < NAR; k += 4) {
    a0 += s_row[k]     * W1[(size_t)k * NH + t];
    a1 += s_row[k + 1] * W1[(size_t)(k + 1) * NH + t];
    a2 += s_row[k + 2] * W1[(size_t)(k + 2) * NH + t];
    a3 += s_row[k + 3] * W1[(size_t)(k + 3) * NH + t];
  }
  float acc = (a0 + a1) + (a2 + a3);
  if (i < NK) g_WpW1[i * NH + t] = acc; else g_bpW1[t] = acc;
}

// ---------------- split-K GEMM: xpart[z] = ar0 slice @ W1 slice ----------------
#define BM 32
#define BN 64
#define BK 16
#define KSL 128
__global__ void gemm_kernel(const float* __restrict__ ar0, const float* __restrict__ W1) {
  __shared__ __align__(16) float As[BK][BM + 1];
  __shared__ __align__(16) float Bs[BK][68];
  int bm = blockIdx.y * BM, bn = blockIdx.x * BN, k0 = blockIdx.z * KSL;
  int t = threadIdx.x;
  int ty = t >> 4, tx = t & 15;
  float acc[2][4] = {{0.f,0.f,0.f,0.f},{0.f,0.f,0.f,0.f}};

  for (int kc = 0; kc < KSL; kc += BK) {
    {
      int m = t >> 3;
      int kk = (t & 7) * 2;
      const float* p = ar0 + (size_t)(bm + m) * NAR + (k0 + kc + kk);
      As[kk][m] = p[0];
      As[kk + 1][m] = p[1];
    }
    {
      int kk = t >> 4;
      int j = (t & 15) * 4;
      const float* p = W1 + (size_t)(k0 + kc + kk) * NH + bn + j;
      Bs[kk][j] = p[0]; Bs[kk][j+1] = p[1]; Bs[kk][j+2] = p[2]; Bs[kk][j+3] = p[3];
    }
    __syncthreads();
    #pragma unroll
    for (int k = 0; k < BK; k++) {
      float a0 = As[k][ty * 2], a1 = As[k][ty * 2 + 1];
      float4 bv = *reinterpret_cast<const float4*>(&Bs[k][tx * 4]);
      acc[0][0] += a0 * bv.x; acc[0][1] += a0 * bv.y; acc[0][2] += a0 * bv.z; acc[0][3] += a0 * bv.w;
      acc[1][0] += a1 * bv.x; acc[1][1] += a1 * bv.y; acc[1][2] += a1 * bv.z; acc[1][3] += a1 * bv.w;
    }
    __syncthreads();
  }
  float* xp = g_xpart + (size_t)blockIdx.z * (NB * NH);
  #pragma unroll
  for (int im = 0; im < 2; im++) {
    int row = bm + ty * 2 + im;
    float* o = xp + (size_t)row * NH + bn + tx * 4;
    o[0] = acc[im][0]; o[1] = acc[im][1]; o[2] = acc[im][2]; o[3] = acc[im][3];
  }
}

// ---------------- persistent per-batch kernel ----------------
// smem (floats):
#define KPT_S   514
#define OFF_KPT  0                   // 32*514 = 16448 (transposed keyproj [h][e])
#define OFF_WX   16448               // 32*129 = 4128 (permuted k*129 + h*4 + g)
#define OFF_WH   20576               // 4128
#define OFF_ZR   24704               // 256
#define OFF_MASK 24960               // 512
#define OFF_H    25472               // 32
#define OFF_O32  25504               // 32
#define OFF_RED  25536               // 16
#define OFF_KEY  25552               // 16 (8 u64)
#define OFF_SUM  25568               // 32
#define SMEM_FLOATS 25600

__global__ __launch_bounds__(256, 2) void persist_kernel(
    const float* __restrict__ ar0, const float* __restrict__ emb,
    const float* __restrict__ Wf, const float* __restrict__ bf,
    const float* __restrict__ Wk, const float* __restrict__ bk,
    const float* __restrict__ W1, const float* __restrict__ b1,
    const float* __restrict__ W2, const float* __restrict__ b2,
    const float* __restrict__ Wx, const float* __restrict__ Wh,
    const float* __restrict__ bl, const float* __restrict__ Wp,
    const float* __restrict__ bp, const float* __restrict__ table,
    const float* __restrict__ selt, float* __restrict__ out)
{
  extern __shared__ float sm[];
  float* s_kpT  = sm + OFF_KPT;
  float* s_Wx   = sm + OFF_WX;
  float* s_Wh   = sm + OFF_WH;
  float* s_zred = sm + OFF_ZR;
  float* s_mask = sm + OFF_MASK;
  float* s_h    = sm + OFF_H;
  float* s_o32  = sm + OFF_O32;
  float* s_red  = sm + OFF_RED;
  ull*   s_key  = (ull*)(sm + OFF_KEY);
  float* s_sum  = sm + OFF_SUM;
  float* s_wk   = sm + OFF_WX;    // prologue alias (8192 <= 8256)

  int b = blockIdx.x, t = threadIdx.x;
  int lane = t & 31, wid = t >> 5;

  int a_act = g_action[b];
  float sel = selt[a_act];

  // ======== prologue A: keyproj^T[b] into smem via FFMA2 register tiles ========
  for (int i = t; i < NC * NK; i += 256) s_wk[i] = Wk[i];
  s_mask[t] = 1.0f; s_mask[t + 256] = 1.0f;
  if (t < 32) { s_h[t] = 0.0f; s_o32[t] = 0.0f; }
  __syncthreads();
  {
    int hg = t & 3, rquad = t >> 2;
    int h0 = hg * 8;
    ull bkp[4];
    #pragma unroll
    for (int j = 0; j < 4; j++) bkp[j] = pack2(bk[h0 + 2*j], bk[h0 + 2*j + 1]);
    const float* embB = emb + (size_t)b * NE * NC;

    #pragma unroll
    for (int pass = 0; pass < 2; pass++) {
      int r0 = pass * 256 + rquad * 4;
      ull acc[4][4];
      #pragma unroll
      for (int i = 0; i < 4; i++)
        #pragma unroll
        for (int j = 0; j < 4; j++) acc[i][j] = bkp[j];

      const float* e0p = embB + (size_t)r0 * NC;
      for (int c = 0; c < NC; c += 4) {
        float4 e0 = *(const float4*)(e0p + c);
        float4 e1 = *(const float4*)(e0p + NC + c);
        float4 e2 = *(const float4*)(e0p + 2 * NC + c);
        float4 e3 = *(const float4*)(e0p + 3 * NC + c);
        #pragma unroll
        for (int cc = 0; cc < 4; cc++) {
          const float* wp = s_wk + (c + cc) * 32 + h0;
          ull w0 = *(const ull*)(wp);
          ull w1 = *(const ull*)(wp + 2);
          ull w2 = *(const ull*)(wp + 4);
          ull w3 = *(const ull*)(wp + 6);
          float c0 = ((const float*)&e0)[cc];
          float c1 = ((const float*)&e1)[cc];
          float c2 = ((const float*)&e2)[cc];
          float c3 = ((const float*)&e3)[cc];
          ull a0 = dup2(c0), a1 = dup2(c1), a2 = dup2(c2), a3 = dup2(c3);
          ffma2(acc[0][0], a0, w0); ffma2(acc[0][1], a0, w1); ffma2(acc[0][2], a0, w2); ffma2(acc[0][3], a0, w3);
          ffma2(acc[1][0], a1, w0); ffma2(acc[1][1], a1, w1); ffma2(acc[1][2], a1, w2); ffma2(acc[1][3], a1, w3);
          ffma2(acc[2][0], a2, w0); ffma2(acc[2][1], a2, w1); ffma2(acc[2][2], a2, w2); ffma2(acc[2][3], a2, w3);
          ffma2(acc[3][0], a3, w0); ffma2(acc[3][1], a3, w1); ffma2(acc[3][2], a3, w2); ffma2(acc[3][3], a3, w3);
        }
      }
      #pragma unroll
      for (int i = 0; i < 4; i++)
        #pragma unroll
        for (int j = 0; j < 4; j++) {
          float2 v = unpack2(acc[i][j]);
          s_kpT[(h0 + 2*j) * KPT_S + r0 + i] = v.x;
          s_kpT[(h0 + 2*j + 1) * KPT_S + r0 + i] = v.y;
        }
    }
  }
  __syncthreads();

  // ======== prologue B: func embed + x0 (s_wk still holds Wk; only reads globals) ========
  float func_r;
  {
    const float* tr = table + (size_t)a_act * 256;
    float a0 = 0.f, a1 = 0.f;
    #pragma unroll 4
    for (int k = 0; k < 256; k += 2) {
      a0 = fmaf(tr[k],     Wf[(size_t)k * 256 + t], a0);
      a1 = fmaf(tr[k + 1], Wf[(size_t)(k + 1) * 256 + t], a1);
    }
    func_r = fmaxf(bf[t] + a0 + a1, 0.0f);
  }
  float x_r = b1[t];
  #pragma unroll
  for (int p = 0; p < 8; p++) x_r += g_xpart[p * (NB * NH) + b * NH + t];

  // register weights
  float wpw1r[32], w2r[32];
  #pragma unroll
  for (int k = 0; k < 32; k++) wpw1r[k] = g_WpW1[k * NH + t];
  #pragma unroll
  for (int j = 0; j < 32; j++) w2r[j] = W2[(size_t)(wid * 32 + j) * 32 + lane];
  float bpw1r = g_bpW1[t];
  float b2r = b2[lane];

  __syncthreads();  // done reading s_wk alias

  // load Wx/Wh permuted: s_Wx[k*129 + h*4 + g] = Wx[k*128 + g*32 + h]
  for (int i = t; i < 4096; i += 256) {
    int k = i >> 7, col = i & 127;
    int g = col >> 5, h = col & 31;
    s_Wx[k * 129 + h * 4 + g] = Wx[i];
    s_Wh[k * 129 + h * 4 + g] = Wh[i];
  }
  // lane roles for LSTM: h = wid*8 + (lane>>2), gate = lane&3
  int lh = wid * 8 + (lane >> 2);
  int lg = lane & 3;
  float blr = bl[lg * 32 + lh];
  float creg = 0.f, sumr = 0.f;
  __syncthreads();

  const float* gumbase = g_gumbel + (size_t)b * NE + 2 * t;

  // ======== 64-step loop ========
  for (int s = 0; s < NSTEPS; s++) {
    // prefetch gumbel pair for entities 2t, 2t+1
    float2 gpair = *(const float2*)(gumbase + (size_t)s * (NB * NE));
    // P1: x update + relu + z2 partial (shuffle) ; read h_prev
    float hpreg = s_h[lane];
    if (s > 0) {
      float xv = x_r + bpw1r;
      #pragma unroll
      for (int k = 0; k < 32; k++) xv = fmaf(s_o32[k], wpw1r[k], xv);
      x_r = xv;
    }
    float tval = fmaxf(func_r + x_r, 0.0f);
    {
      float acc = 0.f;
      #pragma unroll
      for (int j = 0; j < 32; j++)
        acc = fmaf(__shfl_sync(0xffffffffu, tval, j), w2r[j], acc);
      s_zred[t] = acc;
    }
    __syncthreads();

    // P2: all warps: z2 reduce + LSTM (gate,h) per lane + gate combine
    {
      float z2l = b2r;
      #pragma unroll
      for (int p = 0; p < 8; p++) z2l += s_zred[p * 32 + lane];
      float acc = blr;
      const float* wxp = s_Wx + lh * 4 + lg;
      const float* whp = s_Wh + lh * 4 + lg;
      #pragma unroll
      for (int k = 0; k < 32; k++) {
        float z2k = __shfl_sync(0xffffffffu, z2l, k);
        float hk  = __shfl_sync(0xffffffffu, hpreg, k);
        acc = fmaf(z2k, wxp[k * 129], fmaf(hk, whp[k * 129], acc));
      }
      // per-gate transform
      float tg = (lg == 2) ? tanhf(acc) : (1.f / (1.f + expf(-acc)));
      int base = lane & ~3;
      float iv = __shfl_sync(0xffffffffu, tg, base);
      float fv = __shfl_sync(0xffffffffu, tg, base + 1);
      float gv = __shfl_sync(0xffffffffu, tg, base + 2);
      float ov = __shfl_sync(0xffffffffu, tg, base + 3);
      creg = fv * creg + iv * gv;
      float hv = ov * tanhf(creg);
      if (lg == 0) s_h[lh] = hv;
    }
    __syncthreads();

    // P4: attention over entity pair (2t, 2t+1) via FFMA2
    ull acc2 = pack2(0.f, 0.f);
    {
      const float* kbase = s_kpT + 2 * t;
      #pragma unroll
      for (int q = 0; q < 8; q++) {
        float4 hv = *(const float4*)(s_h + 4 * q);
        ffma2(acc2, *(const ull*)(kbase + (4*q + 0) * KPT_S), dup2(hv.x));
        ffma2(acc2, *(const ull*)(kbase + (4*q + 1) * KPT_S), dup2(hv.y));
        ffma2(acc2, *(const ull*)(kbase + (4*q + 2) * KPT_S), dup2(hv.z));
        ffma2(acc2, *(const ull*)(kbase + (4*q + 3) * KPT_S), dup2(hv.w));
      }
    }
    float2 yv = unpack2(acc2);
    float2 mv = *(const float2*)(s_mask + 2 * t);
    float y0 = yv.x * mv.x, y1 = yv.y * mv.y;
    {
      float2 lo = make_float2(y0 * sel, y1 * sel);
      *(float2*)(out + ((size_t)b * NSTEPS + s) * NE + 2 * t) = lo;
    }
    float vmax = fmaxf(y0, y1);
    #pragma unroll
    for (int o = 16; o; o >>= 1) vmax = fmaxf(vmax, __shfl_xor_sync(0xffffffffu, vmax, o));
    if (lane == 0) s_red[wid] = vmax;
    __syncthreads();

    // P5: exp + sum
    float mx = s_red[0];
    #pragma unroll
    for (int i = 1; i < 8; i++) mx = fmaxf(mx, s_red[i]);
    float p0 = expf(y0 - mx), p1 = expf(y1 - mx);
    float ssum = p0 + p1;
    #pragma unroll
    for (int o = 16; o; o >>= 1) ssum += __shfl_xor_sync(0xffffffffu, ssum, o);
    if (lane == 0) s_red[8 + wid] = ssum;
    __syncthreads();

    // P6: keys = p + S*g, warp argmax
    float S = s_red[8];
    #pragma unroll
    for (int i = 1; i < 8; i++) S += s_red[8 + i];
    float v0 = fmaf(S, gpair.x, p0);
    float v1 = fmaf(S, gpair.y, p1);
    ull kA = ((ull)fenc(v0) << 32) | (ull)(0xFFFFFFFFu - (unsigned)(2 * t));
    ull kB = ((ull)fenc(v1) << 32) | (ull)(0xFFFFFFFFu - (unsigned)(2 * t + 1));
    ull km = (kA > kB) ? kA : kB;
    #pragma unroll
    for (int o = 16; o; o >>= 1) {
      ull other = __shfl_xor_sync(0xffffffffu, km, o);
      if (other > km) km = other;
    }
    if (lane == 0) s_key[wid] = km;
    __syncthreads();

    // P7: warp0 finalize
    if (wid == 0) {
      ull kk = (lane < 8) ? s_key[lane] : 0ull;
      #pragma unroll
      for (int o = 4; o; o >>= 1) {
        ull other = __shfl_xor_sync(0xffffffffu, kk, o);
        if (other > kk) kk = other;
      }
      kk = __shfl_sync(0xffffffffu, kk, 0);
      int id = (int)(0xFFFFFFFFu - (unsigned)(kk & 0xFFFFFFFFull));
      float ov = s_kpT[lane * KPT_S + id] - 0.001953125f;  // -1/512
      s_o32[lane] = ov;
      sumr += ov;
      if (lane == 0) {
        s_mask[id] = 0.0f;
        out[OFF_UNITS + (size_t)b * NSTEPS + s] = (float)id * sel;
      }
    }
    __syncthreads();
  }

  // ======== epilogue ========
  if (wid == 0) s_sum[lane] = sumr;
  __syncthreads();
  for (int j = t; j < NAR; j += 256) {
    float acc = ar0[(size_t)b * NAR + j] + 64.0f * bp[j];
    #pragma unroll
    for (int k = 0; k < 32; k++) acc = fmaf(s_sum[k], Wp[(size_t)k * NAR + j], acc);
    out[OFF_AR + (size_t)b * NAR + j] = acc * sel;
  }
}

// ---------------- launcher ----------------
extern "C" void kernel_launch(void* const* d_in, const int* in_sizes, int n_in,
                              void* d_out, int out_size) {
  const float* ar_in   = (const float*)d_in[0];
  const int*   action  = (const int*)  d_in[1];
  const float* emb     = (const float*)d_in[2];
  const float* Wf      = (const float*)d_in[3];
  const float* bf      = (const float*)d_in[4];
  const float* Wk      = (const float*)d_in[5];
  const float* bk      = (const float*)d_in[6];
  const float* W1      = (const float*)d_in[7];
  const float* b1      = (const float*)d_in[8];
  const float* W2      = (const float*)d_in[9];
  const float* b2      = (const float*)d_in[10];
  const float* Wx      = (const float*)d_in[11];
  const float* Wh      = (const float*)d_in[12];
  const float* bl      = (const float*)d_in[13];
  const float* Wp      = (const float*)d_in[14];
  const float* bp      = (const float*)d_in[15];
  const float* table   = (const float*)d_in[16];
  const float* selt    = (const float*)d_in[17];
  float* out = (float*)d_out;

  cudaFuncSetAttribute(persist_kernel, cudaFuncAttributeMaxDynamicSharedMemorySize,
                       SMEM_FLOATS * (int)sizeof(float));

  setup_kernel<<<1, 1>>>(action);
  wpw1_kernel<<<33, 256>>>(Wp, bp, W1);
  gemm_kernel<<<dim3(4, 8, 8), 256>>>(ar_in, W1);
  gumbel_kernel<<<dim3(512, 64), 256>>>();
  persist_kernel<<<256, 256, SMEM_FLOATS * sizeof(float)>>>(
      ar_in, emb, Wf, bf, Wk, bk, W1, b1, W2, b2, Wx, Wh, bl, Wp, bp, table, selt, out);
}

// round 6
// speedup vs baseline: 6.1805x; 1.3251x over previous
#include <cuda_runtime.h>
#include <stdint.h>

#define NB 256
#define NE 512
#define NC 256
#define NAR 1024
#define NH 256
#define NK 32
#define NSTEPS 64

typedef unsigned long long ull;

// ---------------- static device scratch ----------------
__device__ float g_xpart[8 * NB * NH];
__device__ float g_WpW1[NK * NH];
__device__ float g_bpW1[NH];
__device__ float g_gumbel[(size_t)NSTEPS * NB * NE];   // 32 MB
__device__ int   g_action[NB];

#define OFF_UNITS ((size_t)NB * NSTEPS * NE)
#define OFF_AR    (OFF_UNITS + (size_t)NB * NSTEPS)

struct SubKeys { unsigned int a[64]; unsigned int b[64]; };

// ---------------- f32x2 packed helpers ----------------
__device__ __forceinline__ void ffma2(ull &d, ull a, ull b) {
  asm("fma.rn.f32x2 %0, %1, %2, %3;" : "=l"(d) : "l"(a), "l"(b), "l"(d));
}
__device__ __forceinline__ ull dup2(float x) {
  ull r; asm("mov.b64 %0, {%1, %1};" : "=l"(r) : "f"(x)); return r;
}
__device__ __forceinline__ ull pack2(float x, float y) {
  ull r; asm("mov.b64 %0, {%1, %2};" : "=l"(r) : "f"(x), "f"(y)); return r;
}
__device__ __forceinline__ float2 unpack2(ull v) {
  float2 r; asm("mov.b64 {%0, %1}, %2;" : "=f"(r.x), "=f"(r.y) : "l"(v)); return r;
}

// ---------------- Threefry-2x32 (20 rounds), device ----------------
__device__ __forceinline__ void tf2x32(uint32_t k0, uint32_t k1,
                                       uint32_t x0, uint32_t x1,
                                       uint32_t &o0, uint32_t &o1) {
  uint32_t ks2 = k0 ^ k1 ^ 0x1BD11BDAu;
  x0 += k0; x1 += k1;
#define RND(r) { x0 += x1; x1 = __funnelshift_l(x1, x1, (r)); x1 ^= x0; }
  RND(13) RND(15) RND(26) RND(6)   x0 += k1;  x1 += ks2 + 1u;
  RND(17) RND(29) RND(16) RND(24)  x0 += ks2; x1 += k0  + 2u;
  RND(13) RND(15) RND(26) RND(6)   x0 += k0;  x1 += k1  + 3u;
  RND(17) RND(29) RND(16) RND(24)  x0 += k1;  x1 += ks2 + 4u;
  RND(13) RND(15) RND(26) RND(6)   x0 += ks2; x1 += k0  + 5u;
#undef RND
  o0 = x0; o1 = x1;
}

__device__ __forceinline__ float gumbelize(uint32_t bits) {
  float f = __uint_as_float((bits >> 9) | 0x3f800000u) - 1.0f;
  f = fmaxf(f, 1e-20f);
  return -__logf(-__logf(f));
}

__device__ __forceinline__ unsigned fenc(float f) {
  unsigned u = __float_as_uint(f);
  return (u & 0x80000000u) ? ~u : (u | 0x80000000u);
}

// ---------------- action dtype detect + copy ----------------
__global__ void action_kernel(const int* __restrict__ raw) {
  int t = threadIdx.x;
  int odd = (t < 128) ? raw[2 * t + 1] : 0;
  int any = __syncthreads_or(odd != 0);
  g_action[t] = any ? raw[t] : raw[2 * t];
}

// ---------------- fused precompute: wpw1 (33) + gemm (256) + gumbel (8192) ----------------
#define GEMM_BLKS 256
#define GUM_BLKS  8192
__global__ void precompute_kernel(const float* __restrict__ Wp, const float* __restrict__ bp,
                                  const float* __restrict__ W1, const float* __restrict__ ar0,
                                  SubKeys sk) {
  __shared__ __align__(16) float psm[1616];
  int blk = blockIdx.x;
  int t = threadIdx.x;

  if (blk < 33) {
    // ---- WpW1 = Wp@W1, bpW1 = bp@W1 ----
    float* s_row = psm;
    int i = blk;
    for (int k = t; k < NAR; k += 256)
      s_row[k] = (i < NK) ? Wp[(size_t)i * NAR + k] : bp[k];
    __syncthreads();
    float a0 = 0.f, a1 = 0.f, a2 = 0.f, a3 = 0.f;
    for (int k = 0; k < NAR; k += 4) {
      a0 += s_row[k]     * W1[(size_t)k * NH + t];
      a1 += s_row[k + 1] * W1[(size_t)(k + 1) * NH + t];
      a2 += s_row[k + 2] * W1[(size_t)(k + 2) * NH + t];
      a3 += s_row[k + 3] * W1[(size_t)(k + 3) * NH + t];
    }
    float acc = (a0 + a1) + (a2 + a3);
    if (i < NK) g_WpW1[i * NH + t] = acc; else g_bpW1[t] = acc;
  } else if (blk < 33 + GEMM_BLKS) {
    // ---- split-K GEMM: xpart ----
    int flat = blk - 33;
    int bx = flat & 3, by = (flat >> 2) & 7, bz = flat >> 5;
    float* As = psm;            // [16][33]
    float* Bs = psm + 528;      // [16][68]
    int bm = by * 32, bn = bx * 64, k0 = bz * 128;
    int ty = t >> 4, tx = t & 15;
    float acc[2][4] = {{0.f,0.f,0.f,0.f},{0.f,0.f,0.f,0.f}};
    for (int kc = 0; kc < 128; kc += 16) {
      {
        int m = t >> 3;
        int kk = (t & 7) * 2;
        const float* p = ar0 + (size_t)(bm + m) * NAR + (k0 + kc + kk);
        As[kk * 33 + m] = p[0];
        As[(kk + 1) * 33 + m] = p[1];
      }
      {
        int kk = t >> 4;
        int j = (t & 15) * 4;
        const float* p = W1 + (size_t)(k0 + kc + kk) * NH + bn + j;
        Bs[kk * 68 + j] = p[0]; Bs[kk * 68 + j+1] = p[1]; Bs[kk * 68 + j+2] = p[2]; Bs[kk * 68 + j+3] = p[3];
      }
      __syncthreads();
      #pragma unroll
      for (int k = 0; k < 16; k++) {
        float a0 = As[k * 33 + ty * 2], a1 = As[k * 33 + ty * 2 + 1];
        float4 bv = *reinterpret_cast<const float4*>(&Bs[k * 68 + tx * 4]);
        acc[0][0] += a0 * bv.x; acc[0][1] += a0 * bv.y; acc[0][2] += a0 * bv.z; acc[0][3] += a0 * bv.w;
        acc[1][0] += a1 * bv.x; acc[1][1] += a1 * bv.y; acc[1][2] += a1 * bv.z; acc[1][3] += a1 * bv.w;
      }
      __syncthreads();
    }
    float* xp = g_xpart + (size_t)bz * (NB * NH);
    #pragma unroll
    for (int im = 0; im < 2; im++) {
      int row = bm + ty * 2 + im;
      float* o = xp + (size_t)row * NH + bn + tx * 4;
      o[0] = acc[im][0]; o[1] = acc[im][1]; o[2] = acc[im][2]; o[3] = acc[im][3];
    }
  } else {
    // ---- gumbel: 4 values per thread ----
    int gi = blk - (33 + GEMM_BLKS);
    int v0 = gi * 1024 + t * 4;
    int s = v0 >> 17;            // / 131072
    int j = v0 & 131071;
    uint32_t k0 = sk.a[s], k1 = sk.b[s];
    float4 r;
    uint32_t o0, o1;
    tf2x32(k0, k1, 0u, (uint32_t)j,     o0, o1); r.x = gumbelize(o0 ^ o1);
    tf2x32(k0, k1, 0u, (uint32_t)(j+1), o0, o1); r.y = gumbelize(o0 ^ o1);
    tf2x32(k0, k1, 0u, (uint32_t)(j+2), o0, o1); r.z = gumbelize(o0 ^ o1);
    tf2x32(k0, k1, 0u, (uint32_t)(j+3), o0, o1); r.w = gumbelize(o0 ^ o1);
    *(float4*)(g_gumbel + (size_t)s * (NB * NE) + j) = r;
  }
}

// ---------------- persistent per-batch kernel ----------------
#define KPT_S    514
#define OFF_KPT  0          // 32*514 = 16448
#define OFF_WXH  16448      // 32*258 = 8256 (k*258 + h*8 + g*2: +0 wx, +1 wh)
#define OFF_ZR   24704      // 256
#define OFF_PART 24960      // 128
#define OFF_MASK 25088      // 512
#define OFF_H    25600      // 32
#define OFF_HD   25632      // 64 (32 ull: (h,h))
#define OFF_RED  25696      // 16
#define OFF_KEY  25712      // 16 fl (8 ull)
#define OFF_SUM  25728      // 32
#define SMEM_FLOATS 25760

__global__ __launch_bounds__(256, 2) void persist_kernel(
    const float* __restrict__ ar0, const float* __restrict__ emb,
    const float* __restrict__ Wf, const float* __restrict__ bf,
    const float* __restrict__ Wk, const float* __restrict__ bk,
    const float* __restrict__ W1, const float* __restrict__ b1,
    const float* __restrict__ W2, const float* __restrict__ b2,
    const float* __restrict__ Wx, const float* __restrict__ Wh,
    const float* __restrict__ bl, const float* __restrict__ Wp,
    const float* __restrict__ bp, const float* __restrict__ table,
    const float* __restrict__ selt, float* __restrict__ out)
{
  extern __shared__ float sm[];
  float* s_kpT  = sm + OFF_KPT;
  float* s_Wxh  = sm + OFF_WXH;
  float* s_zred = sm + OFF_ZR;
  float* s_part = sm + OFF_PART;
  float* s_mask = sm + OFF_MASK;
  float* s_h    = sm + OFF_H;
  ull*   s_hd   = (ull*)(sm + OFF_HD);
  float* s_red  = sm + OFF_RED;
  ull*   s_key  = (ull*)(sm + OFF_KEY);
  float* s_sum  = sm + OFF_SUM;
  float* s_wk   = sm + OFF_WXH;   // prologue alias (8192 <= 8256)

  int b = blockIdx.x, t = threadIdx.x;
  int lane = t & 31, wid = t >> 5;

  int a_act = g_action[b];
  float sel = selt[a_act];

  // ======== prologue A: keyproj^T[b] into smem via FFMA2 register tiles ========
  for (int i = t; i < NC * NK; i += 256) s_wk[i] = Wk[i];
  s_mask[t] = 1.0f; s_mask[t + 256] = 1.0f;
  if (t < 32) { s_h[t] = 0.0f; s_hd[t] = 0ull; }
  __syncthreads();
  {
    int hg = t & 3, rquad = t >> 2;
    int h0 = hg * 8;
    ull bkp[4];
    #pragma unroll
    for (int j = 0; j < 4; j++) bkp[j] = pack2(bk[h0 + 2*j], bk[h0 + 2*j + 1]);
    const float* embB = emb + (size_t)b * NE * NC;

    #pragma unroll
    for (int pass = 0; pass < 2; pass++) {
      int r0 = pass * 256 + rquad * 4;
      ull acc[4][4];
      #pragma unroll
      for (int i = 0; i < 4; i++)
        #pragma unroll
        for (int j = 0; j < 4; j++) acc[i][j] = bkp[j];

      const float* e0p = embB + (size_t)r0 * NC;
      for (int c = 0; c < NC; c += 4) {
        float4 e0 = *(const float4*)(e0p + c);
        float4 e1 = *(const float4*)(e0p + NC + c);
        float4 e2 = *(const float4*)(e0p + 2 * NC + c);
        float4 e3 = *(const float4*)(e0p + 3 * NC + c);
        #pragma unroll
        for (int cc = 0; cc < 4; cc++) {
          const float* wp = s_wk + (c + cc) * 32 + h0;
          ull w0 = *(const ull*)(wp);
          ull w1 = *(const ull*)(wp + 2);
          ull w2 = *(const ull*)(wp + 4);
          ull w3 = *(const ull*)(wp + 6);
          float c0 = ((const float*)&e0)[cc];
          float c1 = ((const float*)&e1)[cc];
          float c2 = ((const float*)&e2)[cc];
          float c3 = ((const float*)&e3)[cc];
          ull a0 = dup2(c0), a1 = dup2(c1), a2 = dup2(c2), a3 = dup2(c3);
          ffma2(acc[0][0], a0, w0); ffma2(acc[0][1], a0, w1); ffma2(acc[0][2], a0, w2); ffma2(acc[0][3], a0, w3);
          ffma2(acc[1][0], a1, w0); ffma2(acc[1][1], a1, w1); ffma2(acc[1][2], a1, w2); ffma2(acc[1][3], a1, w3);
          ffma2(acc[2][0], a2, w0); ffma2(acc[2][1], a2, w1); ffma2(acc[2][2], a2, w2); ffma2(acc[2][3], a2, w3);
          ffma2(acc[3][0], a3, w0); ffma2(acc[3][1], a3, w1); ffma2(acc[3][2], a3, w2); ffma2(acc[3][3], a3, w3);
        }
      }
      #pragma unroll
      for (int i = 0; i < 4; i++)
        #pragma unroll
        for (int j = 0; j < 4; j++) {
          float2 v = unpack2(acc[i][j]);
          s_kpT[(h0 + 2*j) * KPT_S + r0 + i] = v.x;
          s_kpT[(h0 + 2*j + 1) * KPT_S + r0 + i] = v.y;
        }
    }
  }
  __syncthreads();

  // ======== prologue B: func embed + x0 + register weights ========
  float func_r;
  {
    const float* tr = table + (size_t)a_act * 256;
    float a0 = 0.f, a1 = 0.f;
    #pragma unroll 4
    for (int k = 0; k < 256; k += 2) {
      a0 = fmaf(tr[k],     Wf[(size_t)k * 256 + t], a0);
      a1 = fmaf(tr[k + 1], Wf[(size_t)(k + 1) * 256 + t], a1);
    }
    func_r = fmaxf(bf[t] + a0 + a1, 0.0f);
  }
  float x_r = b1[t];
  #pragma unroll
  for (int p = 0; p < 8; p++) x_r += g_xpart[p * (NB * NH) + b * NH + t];

  float wpw1r[32], w2r[32];
  float csum = 0.f;
  #pragma unroll
  for (int k = 0; k < 32; k++) { wpw1r[k] = g_WpW1[k * NH + t]; csum += wpw1r[k]; }
  #pragma unroll
  for (int j = 0; j < 32; j++) w2r[j] = W2[(size_t)(wid * 32 + j) * 32 + lane];
  float bpw1c = g_bpW1[t] - 0.001953125f * csum;   // fold -1/512 * sum(wpw1)
  float b2r = b2[lane];

  __syncthreads();  // done reading s_wk alias

  // fill interleaved Wxh: s_Wxh[k*258 + h*8 + g*2 + {0,1}] = {Wx, Wh}[k*128 + g*32 + h]
  for (int i = t; i < 4096; i += 256) {
    int k = i >> 7, col = i & 127;
    int g = col >> 5, h = col & 31;
    s_Wxh[k * 258 + h * 8 + g * 2]     = Wx[i];
    s_Wxh[k * 258 + h * 8 + g * 2 + 1] = Wh[i];
  }
  // LSTM roles: khalf = wid>>2, lh = (wid&3)*8 + (lane>>2) in [0,32), lg = lane&3
  int khalf = wid >> 2;
  int lh = (wid & 3) * 8 + (lane >> 2);
  int lg = lane & 3;
  float blr = bl[lg * 32 + lh];
  float creg = 0.f, sumr = 0.f;
  __syncthreads();

  const float* gumbase = g_gumbel + (size_t)b * NE + 2 * t;

  // ======== 64-step loop ========
  for (int s = 0; s < NSTEPS; s++) {
    float2 gpair = *(const float2*)(gumbase + (size_t)s * (NB * NE));
    float hpreg = s_h[lane];

    // ---- A: finalize prev selection (all threads) + x update + relu + z2 partial ----
    if (s > 0) {
      ull kk = s_key[0];
      #pragma unroll
      for (int i = 1; i < 8; i++) { ull o = s_key[i]; if (o > kk) kk = o; }
      int id = (int)(0xFFFFFFFFu - (unsigned)(kk & 0xFFFFFFFFull));
      float xv = x_r + bpw1c;
      const float* kc = s_kpT + id;
      #pragma unroll
      for (int k = 0; k < 32; k++) xv = fmaf(kc[k * KPT_S], wpw1r[k], xv);
      x_r = xv;
      if (wid == 0) sumr += s_kpT[lane * KPT_S + id] - 0.001953125f;
      if (t == 0) {
        s_mask[id] = 0.0f;
        out[OFF_UNITS + (size_t)b * NSTEPS + (s - 1)] = (float)id * sel;
      }
    }
    float tval = fmaxf(func_r + x_r, 0.0f);
    {
      float acc = 0.f;
      #pragma unroll
      for (int j = 0; j < 32; j++)
        acc = fmaf(__shfl_sync(0xffffffffu, tval, j), w2r[j], acc);
      s_zred[t] = acc;
    }
    __syncthreads();

    // ---- B: z2 reduce + split-K LSTM ----
    float z2l = b2r;
    #pragma unroll
    for (int p = 0; p < 8; p++) z2l += s_zred[p * 32 + lane];
    {
      float acc = (khalf == 0) ? blr : 0.f;
      const float* wbase = s_Wxh + lh * 8 + lg * 2 + khalf * (16 * 258);
      #pragma unroll
      for (int k16 = 0; k16 < 16; k16++) {
        int k = khalf * 16 + k16;
        float z2k = __shfl_sync(0xffffffffu, z2l, k);
        float hk  = __shfl_sync(0xffffffffu, hpreg, k);
        float2 wv = unpack2(*(const ull*)(wbase + k16 * 258));
        acc = fmaf(z2k, wv.x, fmaf(hk, wv.y, acc));
      }
      if (khalf == 1) s_part[lh * 4 + lg] = acc;
      __syncthreads();
      if (khalf == 0) {
        acc += s_part[lh * 4 + lg];
        // gate transform: lg 0,1,3 sigmoid; lg 2 tanh
        float e2 = __expf((lg == 2) ? (2.f * acc) : (-acc));
        float tg = (lg == 2) ? (1.f - __fdividef(2.f, e2 + 1.f))
                             : __fdividef(1.f, 1.f + e2);
        int base = lane & ~3;
        float iv = __shfl_sync(0xffffffffu, tg, base);
        float fv = __shfl_sync(0xffffffffu, tg, base + 1);
        float gv = __shfl_sync(0xffffffffu, tg, base + 2);
        float ov = __shfl_sync(0xffffffffu, tg, base + 3);
        creg = fv * creg + iv * gv;
        float e2c = __expf(2.f * creg);
        float hv = ov * (1.f - __fdividef(2.f, e2c + 1.f));
        if (lg == 0) { s_h[lh] = hv; s_hd[lh] = dup2(hv); }
      }
    }
    __syncthreads();

    // ---- C: attention + logits + exp + warp sum (no max subtraction) ----
    ull acc2 = pack2(0.f, 0.f);
    {
      const float* kb = s_kpT + 2 * t;
      #pragma unroll
      for (int k = 0; k < 32; k++)
        ffma2(acc2, *(const ull*)(kb + k * KPT_S), s_hd[k]);
    }
    float2 yv = unpack2(acc2);
    float2 mv = *(const float2*)(s_mask + 2 * t);
    float y0 = yv.x * mv.x, y1 = yv.y * mv.y;
    *(float2*)(out + ((size_t)b * NSTEPS + s) * NE + 2 * t) = make_float2(y0 * sel, y1 * sel);
    float p0 = __expf(y0), p1 = __expf(y1);
    float ssum = p0 + p1;
    #pragma unroll
    for (int o = 16; o; o >>= 1) ssum += __shfl_xor_sync(0xffffffffu, ssum, o);
    if (lane == 0) s_red[wid] = ssum;
    __syncthreads();

    // ---- E: S, keys, argmax ----
    float S = s_red[0];
    #pragma unroll
    for (int i = 1; i < 8; i++) S += s_red[i];
    float v0 = fmaf(S, gpair.x, p0);
    float v1 = fmaf(S, gpair.y, p1);
    ull kA = ((ull)fenc(v0) << 32) | (ull)(0xFFFFFFFFu - (unsigned)(2 * t));
    ull kB = ((ull)fenc(v1) << 32) | (ull)(0xFFFFFFFFu - (unsigned)(2 * t + 1));
    ull km = (kA > kB) ? kA : kB;
    #pragma unroll
    for (int o = 16; o; o >>= 1) {
      ull other = __shfl_xor_sync(0xffffffffu, km, o);
      if (other > km) km = other;
    }
    if (lane == 0) s_key[wid] = km;
    __syncthreads();
  }

  // ======== final selection (step 63) ========
  {
    ull kk = s_key[0];
    #pragma unroll
    for (int i = 1; i < 8; i++) { ull o = s_key[i]; if (o > kk) kk = o; }
    int id = (int)(0xFFFFFFFFu - (unsigned)(kk & 0xFFFFFFFFull));
    if (wid == 0) sumr += s_kpT[lane * KPT_S + id] - 0.001953125f;
    if (t == 0) out[OFF_UNITS + (size_t)b * NSTEPS + (NSTEPS - 1)] = (float)id * sel;
  }
  if (wid == 0) s_sum[lane] = sumr;
  __syncthreads();

  // ======== epilogue: ar_out = (ar0 + sum@Wp + 64*bp) * sel ========
  for (int j = t; j < NAR; j += 256) {
    float acc = ar0[(size_t)b * NAR + j] + 64.0f * bp[j];
    #pragma unroll
    for (int k = 0; k < 32; k++) acc = fmaf(s_sum[k], Wp[(size_t)k * NAR + j], acc);
    out[OFF_AR + (size_t)b * NAR + j] = acc * sel;
  }
}

// ---------------- host threefry for the subkey chain ----------------
static inline void h_tf2x32(uint32_t k0, uint32_t k1, uint32_t x0, uint32_t x1,
                            uint32_t &o0, uint32_t &o1) {
  uint32_t ks2 = k0 ^ k1 ^ 0x1BD11BDAu;
  x0 += k0; x1 += k1;
#define HRND(r) { x0 += x1; x1 = (x1 << (r)) | (x1 >> (32 - (r))); x1 ^= x0; }
  HRND(13) HRND(15) HRND(26) HRND(6)   x0 += k1;  x1 += ks2 + 1u;
  HRND(17) HRND(29) HRND(16) HRND(24)  x0 += ks2; x1 += k0  + 2u;
  HRND(13) HRND(15) HRND(26) HRND(6)   x0 += k0;  x1 += k1  + 3u;
  HRND(17) HRND(29) HRND(16) HRND(24)  x0 += k1;  x1 += ks2 + 4u;
  HRND(13) HRND(15) HRND(26) HRND(6)   x0 += ks2; x1 += k0  + 5u;
#undef HRND
  o0 = x0; o1 = x1;
}

// ---------------- launcher ----------------
extern "C" void kernel_launch(void* const* d_in, const int* in_sizes, int n_in,
                              void* d_out, int out_size) {
  const float* ar_in   = (const float*)d_in[0];
  const int*   action  = (const int*)  d_in[1];
  const float* emb     = (const float*)d_in[2];
  const float* Wf      = (const float*)d_in[3];
  const float* bf      = (const float*)d_in[4];
  const float* Wk      = (const float*)d_in[5];
  const float* bk      = (const float*)d_in[6];
  const float* W1      = (const float*)d_in[7];
  const float* b1      = (const float*)d_in[8];
  const float* W2      = (const float*)d_in[9];
  const float* b2      = (const float*)d_in[10];
  const float* Wx      = (const float*)d_in[11];
  const float* Wh      = (const float*)d_in[12];
  const float* bl      = (const float*)d_in[13];
  const float* Wp      = (const float*)d_in[14];
  const float* bp      = (const float*)d_in[15];
  const float* table   = (const float*)d_in[16];
  const float* selt    = (const float*)d_in[17];
  float* out = (float*)d_out;

  // subkey chain (constant, computed on host every call)
  SubKeys sk;
  {
    uint32_t k0 = 0u, k1 = 42u;
    for (int s = 0; s < NSTEPS; s++) {
      uint32_t n0, n1, s0, s1;
      h_tf2x32(k0, k1, 0u, 0u, n0, n1);
      h_tf2x32(k0, k1, 0u, 1u, s0, s1);
      sk.a[s] = s0; sk.b[s] = s1;
      k0 = n0; k1 = n1;
    }
  }

  cudaFuncSetAttribute(persist_kernel, cudaFuncAttributeMaxDynamicSharedMemorySize,
                       SMEM_FLOATS * (int)sizeof(float));

  action_kernel<<<1, 256>>>(action);
  precompute_kernel<<<33 + GEMM_BLKS + GUM_BLKS, 256>>>(Wp, bp, W1, ar_in, sk);
  persist_kernel<<<256, 256, SMEM_FLOATS * sizeof(float)>>>(
      ar_in, emb, Wf, bf, Wk, bk, W1, b1, W2, b2, Wx, Wh, bl, Wp, bp, table, selt, out);
}

// round 7
// speedup vs baseline: 6.4001x; 1.0355x over previous
#include <cuda_runtime.h>
#include <stdint.h>

#define NB 256
#define NE 512
#define NC 256
#define NAR 1024
#define NH 256
#define NK 32
#define NSTEPS 64

typedef unsigned long long ull;

// ---------------- static device scratch ----------------
__device__ float g_xpart[8 * NB * NH];
__device__ float g_WpW1[NK * NH];
__device__ float g_bpW1[NH];
__device__ float g_gumbel[(size_t)NB * NSTEPS * NE];   // 32 MB, layout [b][s][e]
__device__ int   g_action[NB];

#define OFF_UNITS ((size_t)NB * NSTEPS * NE)
#define OFF_AR    (OFF_UNITS + (size_t)NB * NSTEPS)

struct SubKeys { unsigned int a[64]; unsigned int b[64]; };

// ---------------- f32x2 packed helpers ----------------
__device__ __forceinline__ void ffma2(ull &d, ull a, ull b) {
  asm("fma.rn.f32x2 %0, %1, %2, %3;" : "=l"(d) : "l"(a), "l"(b), "l"(d));
}
__device__ __forceinline__ ull fadd2(ull a, ull b) {
  ull r; asm("add.rn.f32x2 %0, %1, %2;" : "=l"(r) : "l"(a), "l"(b)); return r;
}
__device__ __forceinline__ ull dup2(float x) {
  ull r; asm("mov.b64 %0, {%1, %1};" : "=l"(r) : "f"(x)); return r;
}
__device__ __forceinline__ ull pack2(float x, float y) {
  ull r; asm("mov.b64 %0, {%1, %2};" : "=l"(r) : "f"(x), "f"(y)); return r;
}
__device__ __forceinline__ float2 unpack2(ull v) {
  float2 r; asm("mov.b64 {%0, %1}, %2;" : "=f"(r.x), "=f"(r.y) : "l"(v)); return r;
}

// ---------------- Threefry-2x32 (20 rounds), device ----------------
__device__ __forceinline__ void tf2x32(uint32_t k0, uint32_t k1,
                                       uint32_t x0, uint32_t x1,
                                       uint32_t &o0, uint32_t &o1) {
  uint32_t ks2 = k0 ^ k1 ^ 0x1BD11BDAu;
  x0 += k0; x1 += k1;
#define RND(r) { x0 += x1; x1 = __funnelshift_l(x1, x1, (r)); x1 ^= x0; }
  RND(13) RND(15) RND(26) RND(6)   x0 += k1;  x1 += ks2 + 1u;
  RND(17) RND(29) RND(16) RND(24)  x0 += ks2; x1 += k0  + 2u;
  RND(13) RND(15) RND(26) RND(6)   x0 += k0;  x1 += k1  + 3u;
  RND(17) RND(29) RND(16) RND(24)  x0 += k1;  x1 += ks2 + 4u;
  RND(13) RND(15) RND(26) RND(6)   x0 += ks2; x1 += k0  + 5u;
#undef RND
  o0 = x0; o1 = x1;
}

__device__ __forceinline__ float gumbelize(uint32_t bits) {
  float f = __uint_as_float((bits >> 9) | 0x3f800000u) - 1.0f;
  f = fmaxf(f, 1e-20f);
  return -__logf(-__logf(f));
}

__device__ __forceinline__ unsigned fenc(float f) {
  unsigned u = __float_as_uint(f);
  return (u & 0x80000000u) ? ~u : (u | 0x80000000u);
}

// ---------------- fused precompute ----------------
#define GEMM_BLKS 256
#define GUM_BLKS  8192
// blocks: [0,33) wpw1 | [33, 33+256) gemm | 289 action | [290, 290+8192) gumbel
__global__ void precompute_kernel(const float* __restrict__ Wp, const float* __restrict__ bp,
                                  const float* __restrict__ W1, const float* __restrict__ ar0,
                                  const int* __restrict__ action_raw, SubKeys sk) {
  __shared__ __align__(16) float psm[1616];
  int blk = blockIdx.x;
  int t = threadIdx.x;

  if (blk < 33) {
    float* s_row = psm;
    int i = blk;
    for (int k = t; k < NAR; k += 256)
      s_row[k] = (i < NK) ? Wp[(size_t)i * NAR + k] : bp[k];
    __syncthreads();
    float a0 = 0.f, a1 = 0.f, a2 = 0.f, a3 = 0.f;
    for (int k = 0; k < NAR; k += 4) {
      a0 += s_row[k]     * W1[(size_t)k * NH + t];
      a1 += s_row[k + 1] * W1[(size_t)(k + 1) * NH + t];
      a2 += s_row[k + 2] * W1[(size_t)(k + 2) * NH + t];
      a3 += s_row[k + 3] * W1[(size_t)(k + 3) * NH + t];
    }
    float acc = (a0 + a1) + (a2 + a3);
    if (i < NK) g_WpW1[i * NH + t] = acc; else g_bpW1[t] = acc;
  } else if (blk < 33 + GEMM_BLKS) {
    int flat = blk - 33;
    int bx = flat & 3, by = (flat >> 2) & 7, bz = flat >> 5;
    float* As = psm;            // [16][33]
    float* Bs = psm + 528;      // [16][68]
    int bm = by * 32, bn = bx * 64, k0 = bz * 128;
    int ty = t >> 4, tx = t & 15;
    float acc[2][4] = {{0.f,0.f,0.f,0.f},{0.f,0.f,0.f,0.f}};
    for (int kc = 0; kc < 128; kc += 16) {
      {
        int m = t >> 3;
        int kk = (t & 7) * 2;
        const float* p = ar0 + (size_t)(bm + m) * NAR + (k0 + kc + kk);
        As[kk * 33 + m] = p[0];
        As[(kk + 1) * 33 + m] = p[1];
      }
      {
        int kk = t >> 4;
        int j = (t & 15) * 4;
        const float* p = W1 + (size_t)(k0 + kc + kk) * NH + bn + j;
        Bs[kk * 68 + j] = p[0]; Bs[kk * 68 + j+1] = p[1]; Bs[kk * 68 + j+2] = p[2]; Bs[kk * 68 + j+3] = p[3];
      }
      __syncthreads();
      #pragma unroll
      for (int k = 0; k < 16; k++) {
        float a0 = As[k * 33 + ty * 2], a1 = As[k * 33 + ty * 2 + 1];
        float4 bv = *reinterpret_cast<const float4*>(&Bs[k * 68 + tx * 4]);
        acc[0][0] += a0 * bv.x; acc[0][1] += a0 * bv.y; acc[0][2] += a0 * bv.z; acc[0][3] += a0 * bv.w;
        acc[1][0] += a1 * bv.x; acc[1][1] += a1 * bv.y; acc[1][2] += a1 * bv.z; acc[1][3] += a1 * bv.w;
      }
      __syncthreads();
    }
    float* xp = g_xpart + (size_t)bz * (NB * NH);
    #pragma unroll
    for (int im = 0; im < 2; im++) {
      int row = bm + ty * 2 + im;
      float* o = xp + (size_t)row * NH + bn + tx * 4;
      o[0] = acc[im][0]; o[1] = acc[im][1]; o[2] = acc[im][2]; o[3] = acc[im][3];
    }
  } else if (blk == 33 + GEMM_BLKS) {
    int odd = (t < 128) ? action_raw[2 * t + 1] : 0;
    int any = __syncthreads_or(odd != 0);
    g_action[t] = any ? action_raw[t] : action_raw[2 * t];
  } else {
    // gumbel: 4 consecutive e per thread, layout [b][s][e]
    int gi = blk - (34 + GEMM_BLKS);
    int v0 = gi * 1024 + t * 4;          // linear over b*32768 + s*512 + e
    int b = v0 >> 15;
    int rem = v0 & 32767;
    int s = rem >> 9;
    int e = rem & 511;
    int j = b * 512 + e;                 // threefry counter within step s
    uint32_t k0 = sk.a[s], k1 = sk.b[s];
    float4 r;
    uint32_t o0, o1;
    tf2x32(k0, k1, 0u, (uint32_t)j,     o0, o1); r.x = gumbelize(o0 ^ o1);
    tf2x32(k0, k1, 0u, (uint32_t)(j+1), o0, o1); r.y = gumbelize(o0 ^ o1);
    tf2x32(k0, k1, 0u, (uint32_t)(j+2), o0, o1); r.z = gumbelize(o0 ^ o1);
    tf2x32(k0, k1, 0u, (uint32_t)(j+3), o0, o1); r.w = gumbelize(o0 ^ o1);
    *(float4*)(g_gumbel + (size_t)v0) = r;
  }
}

// ---------------- persistent per-batch kernel ----------------
#define KPT_S    514
#define OFF_KPT  0          // 32*514 = 16448
#define OFF_WXH  16448      // 32*258 = 8256
#define OFF_ZR   24704      // 256
#define OFF_T    24960      // 256
#define OFF_PART 25216      // 128
#define OFF_H    25344      // 32
#define OFF_HD   25376      // 64 (32 ull)
#define OFF_RED  25440      // 16
#define OFF_KEY  25456      // 16 fl (8 ull)
#define OFF_SUM  25472      // 32
#define SMEM_FLOATS 25504

__global__ __launch_bounds__(256, 2) void persist_kernel(
    const float* __restrict__ ar0, const float* __restrict__ emb,
    const float* __restrict__ Wf, const float* __restrict__ bf,
    const float* __restrict__ Wk, const float* __restrict__ bk,
    const float* __restrict__ W1, const float* __restrict__ b1,
    const float* __restrict__ W2, const float* __restrict__ b2,
    const float* __restrict__ Wx, const float* __restrict__ Wh,
    const float* __restrict__ bl, const float* __restrict__ Wp,
    const float* __restrict__ bp, const float* __restrict__ table,
    const float* __restrict__ selt, float* __restrict__ out)
{
  extern __shared__ float sm[];
  float* s_kpT  = sm + OFF_KPT;
  float* s_Wxh  = sm + OFF_WXH;
  float* s_zred = sm + OFF_ZR;
  float* s_t    = sm + OFF_T;
  float* s_part = sm + OFF_PART;
  float* s_h    = sm + OFF_H;
  ull*   s_hd   = (ull*)(sm + OFF_HD);
  float* s_red  = sm + OFF_RED;
  ull*   s_key  = (ull*)(sm + OFF_KEY);
  float* s_sum  = sm + OFF_SUM;
  float* s_wk   = sm + OFF_WXH;   // prologue alias

  int b = blockIdx.x, t = threadIdx.x;
  int lane = t & 31, wid = t >> 5;

  int a_act = g_action[b];
  float sel = selt[a_act];

  // ======== prologue A: keyproj^T[b] into smem ========
  for (int i = t; i < NC * NK; i += 256) s_wk[i] = Wk[i];
  if (t < 32) { s_h[t] = 0.0f; s_hd[t] = 0ull; }
  __syncthreads();
  {
    int hg = t & 3, rquad = t >> 2;
    int h0 = hg * 8;
    ull bkp[4];
    #pragma unroll
    for (int j = 0; j < 4; j++) bkp[j] = pack2(bk[h0 + 2*j], bk[h0 + 2*j + 1]);
    const float* embB = emb + (size_t)b * NE * NC;

    #pragma unroll
    for (int pass = 0; pass < 2; pass++) {
      int r0 = pass * 256 + rquad * 4;
      ull acc[4][4];
      #pragma unroll
      for (int i = 0; i < 4; i++)
        #pragma unroll
        for (int j = 0; j < 4; j++) acc[i][j] = bkp[j];

      const float* e0p = embB + (size_t)r0 * NC;
      for (int c = 0; c < NC; c += 4) {
        float4 e0 = *(const float4*)(e0p + c);
        float4 e1 = *(const float4*)(e0p + NC + c);
        float4 e2 = *(const float4*)(e0p + 2 * NC + c);
        float4 e3 = *(const float4*)(e0p + 3 * NC + c);
        #pragma unroll
        for (int cc = 0; cc < 4; cc++) {
          const float* wp = s_wk + (c + cc) * 32 + h0;
          ull w0 = *(const ull*)(wp);
          ull w1 = *(const ull*)(wp + 2);
          ull w2 = *(const ull*)(wp + 4);
          ull w3 = *(const ull*)(wp + 6);
          float c0 = ((const float*)&e0)[cc];
          float c1 = ((const float*)&e1)[cc];
          float c2 = ((const float*)&e2)[cc];
          float c3 = ((const float*)&e3)[cc];
          ull a0 = dup2(c0), a1 = dup2(c1), a2 = dup2(c2), a3 = dup2(c3);
          ffma2(acc[0][0], a0, w0); ffma2(acc[0][1], a0, w1); ffma2(acc[0][2], a0, w2); ffma2(acc[0][3], a0, w3);
          ffma2(acc[1][0], a1, w0); ffma2(acc[1][1], a1, w1); ffma2(acc[1][2], a1, w2); ffma2(acc[1][3], a1, w3);
          ffma2(acc[2][0], a2, w0); ffma2(acc[2][1], a2, w1); ffma2(acc[2][2], a2, w2); ffma2(acc[2][3], a2, w3);
          ffma2(acc[3][0], a3, w0); ffma2(acc[3][1], a3, w1); ffma2(acc[3][2], a3, w2); ffma2(acc[3][3], a3, w3);
        }
      }
      #pragma unroll
      for (int i = 0; i < 4; i++)
        #pragma unroll
        for (int j = 0; j < 4; j++) {
          float2 v = unpack2(acc[i][j]);
          s_kpT[(h0 + 2*j) * KPT_S + r0 + i] = v.x;
          s_kpT[(h0 + 2*j + 1) * KPT_S + r0 + i] = v.y;
        }
    }
  }
  __syncthreads();

  // ======== prologue B: func embed + x0 + register weights ========
  float func_r;
  {
    const float* tr = table + (size_t)a_act * 256;
    float a0 = 0.f, a1 = 0.f;
    #pragma unroll 4
    for (int k = 0; k < 256; k += 2) {
      a0 = fmaf(tr[k],     Wf[(size_t)k * 256 + t], a0);
      a1 = fmaf(tr[k + 1], Wf[(size_t)(k + 1) * 256 + t], a1);
    }
    func_r = fmaxf(bf[t] + a0 + a1, 0.0f);
  }
  float x_r = b1[t];
  #pragma unroll
  for (int p = 0; p < 8; p++) x_r += g_xpart[p * (NB * NH) + b * NH + t];

  float wpw1r[32];
  ull w2p[16];
  float csum = 0.f;
  #pragma unroll
  for (int k = 0; k < 32; k++) { wpw1r[k] = g_WpW1[k * NH + t]; csum += wpw1r[k]; }
  #pragma unroll
  for (int j = 0; j < 16; j++)
    w2p[j] = pack2(W2[(size_t)(wid * 32 + 2*j) * 32 + lane],
                   W2[(size_t)(wid * 32 + 2*j + 1) * 32 + lane]);
  float bpw1c = g_bpW1[t] - 0.001953125f * csum;
  float b2r = b2[lane];

  __syncthreads();

  for (int i = t; i < 4096; i += 256) {
    int k = i >> 7, col = i & 127;
    int g = col >> 5, h = col & 31;
    s_Wxh[k * 258 + h * 8 + g * 2]     = Wx[i];
    s_Wxh[k * 258 + h * 8 + g * 2 + 1] = Wh[i];
  }
  int khalf = wid >> 2;
  int lh = (wid & 3) * 8 + (lane >> 2);
  int lg = lane & 3;
  float blr = bl[lg * 32 + lh];
  float creg = 0.f, sumr = 0.f;
  float m0 = 1.0f, m1 = 1.0f;    // mask registers for entities 2t, 2t+1
  __syncthreads();

  const float* gumbase = g_gumbel + (size_t)b * (NSTEPS * NE) + 2 * t;

  // ======== 64-step loop ========
  for (int s = 0; s < NSTEPS; s++) {
    float2 gpair = *(const float2*)(gumbase + s * NE);
    float hpreg = s_h[lane];

    // ---- A: finalize prev selection + x update + relu + z2 partial ----
    if (s > 0) {
      ull kk = s_key[0];
      #pragma unroll
      for (int i = 1; i < 8; i++) { ull o = s_key[i]; if (o > kk) kk = o; }
      int id = (int)(0xFFFFFFFFu - (unsigned)(kk & 0xFFFFFFFFull));
      if (id == 2 * t) m0 = 0.0f;
      if (id == 2 * t + 1) m1 = 0.0f;
      const float* kc = s_kpT + id;
      float xv0 = x_r + bpw1c, xv1 = 0.f, xv2 = 0.f, xv3 = 0.f;
      #pragma unroll
      for (int k = 0; k < 32; k += 4) {
        xv0 = fmaf(kc[(k + 0) * KPT_S], wpw1r[k + 0], xv0);
        xv1 = fmaf(kc[(k + 1) * KPT_S], wpw1r[k + 1], xv1);
        xv2 = fmaf(kc[(k + 2) * KPT_S], wpw1r[k + 2], xv2);
        xv3 = fmaf(kc[(k + 3) * KPT_S], wpw1r[k + 3], xv3);
      }
      x_r = (xv0 + xv1) + (xv2 + xv3);
      if (wid == 0) sumr += s_kpT[lane * KPT_S + id] - 0.001953125f;
      if (t == 0) out[OFF_UNITS + (size_t)b * NSTEPS + (s - 1)] = (float)id * sel;
    }
    float tval = fmaxf(func_r + x_r, 0.0f);
    s_t[t] = tval;
    __syncwarp();
    {
      const ull* tp = (const ull*)(s_t + wid * 32);
      ull za = 0ull, zb = 0ull;
      #pragma unroll
      for (int j = 0; j < 16; j += 2) {
        ffma2(za, tp[j], w2p[j]);
        ffma2(zb, tp[j + 1], w2p[j + 1]);
      }
      float2 zv = unpack2(fadd2(za, zb));
      s_zred[t] = zv.x + zv.y;
    }
    __syncthreads();

    // ---- B: z2 reduce + split-K LSTM ----
    float z2l;
    {
      float r0 = s_zred[lane]        + s_zred[32 + lane];
      float r1 = s_zred[64 + lane]   + s_zred[96 + lane];
      float r2 = s_zred[128 + lane]  + s_zred[160 + lane];
      float r3 = s_zred[192 + lane]  + s_zred[224 + lane];
      z2l = b2r + ((r0 + r1) + (r2 + r3));
    }
    {
      float accA = (khalf == 0) ? blr : 0.f, accB = 0.f;
      const float* wbase = s_Wxh + lh * 8 + lg * 2 + khalf * (16 * 258);
      #pragma unroll
      for (int k16 = 0; k16 < 16; k16 += 2) {
        int k = khalf * 16 + k16;
        float z2a = __shfl_sync(0xffffffffu, z2l, k);
        float ha  = __shfl_sync(0xffffffffu, hpreg, k);
        float2 wa = unpack2(*(const ull*)(wbase + k16 * 258));
        accA = fmaf(z2a, wa.x, fmaf(ha, wa.y, accA));
        float z2b = __shfl_sync(0xffffffffu, z2l, k + 1);
        float hb  = __shfl_sync(0xffffffffu, hpreg, k + 1);
        float2 wb = unpack2(*(const ull*)(wbase + (k16 + 1) * 258));
        accB = fmaf(z2b, wb.x, fmaf(hb, wb.y, accB));
      }
      float acc = accA + accB;
      if (khalf == 1) s_part[lh * 4 + lg] = acc;
      __syncthreads();
      if (khalf == 0) {
        acc += s_part[lh * 4 + lg];
        float e2 = __expf((lg == 2) ? (2.f * acc) : (-acc));
        float tg = (lg == 2) ? (1.f - __fdividef(2.f, e2 + 1.f))
                             : __fdividef(1.f, 1.f + e2);
        int base = lane & ~3;
        float iv = __shfl_sync(0xffffffffu, tg, base);
        float fv = __shfl_sync(0xffffffffu, tg, base + 1);
        float gv = __shfl_sync(0xffffffffu, tg, base + 2);
        float ov = __shfl_sync(0xffffffffu, tg, base + 3);
        creg = fv * creg + iv * gv;
        float e2c = __expf(2.f * creg);
        float hv = ov * (1.f - __fdividef(2.f, e2c + 1.f));
        if (lg == 0) { s_h[lh] = hv; s_hd[lh] = dup2(hv); }
      }
    }
    __syncthreads();

    // ---- C: attention (4 packed accumulators) + exp + warp sum ----
    ull a0 = 0ull, a1 = 0ull, a2 = 0ull, a3 = 0ull;
    {
      const float* kb = s_kpT + 2 * t;
      #pragma unroll
      for (int q = 0; q < 8; q++) {
        ffma2(a0, *(const ull*)(kb + (4*q + 0) * KPT_S), s_hd[4*q + 0]);
        ffma2(a1, *(const ull*)(kb + (4*q + 1) * KPT_S), s_hd[4*q + 1]);
        ffma2(a2, *(const ull*)(kb + (4*q + 2) * KPT_S), s_hd[4*q + 2]);
        ffma2(a3, *(const ull*)(kb + (4*q + 3) * KPT_S), s_hd[4*q + 3]);
      }
    }
    float2 yv = unpack2(fadd2(fadd2(a0, a1), fadd2(a2, a3)));
    float y0 = yv.x * m0, y1 = yv.y * m1;
    __stcs((float2*)(out + ((size_t)b * NSTEPS + s) * NE + 2 * t),
           make_float2(y0 * sel, y1 * sel));
    float p0 = __expf(y0), p1 = __expf(y1);
    float ssum = p0 + p1;
    #pragma unroll
    for (int o = 16; o; o >>= 1) ssum += __shfl_xor_sync(0xffffffffu, ssum, o);
    if (lane == 0) s_red[wid] = ssum;
    __syncthreads();

    // ---- E: S, keys, argmax ----
    float S;
    {
      float r0 = s_red[0] + s_red[1], r1 = s_red[2] + s_red[3];
      float r2 = s_red[4] + s_red[5], r3 = s_red[6] + s_red[7];
      S = (r0 + r1) + (r2 + r3);
    }
    float v0 = fmaf(S, gpair.x, p0);
    float v1 = fmaf(S, gpair.y, p1);
    ull kA = ((ull)fenc(v0) << 32) | (ull)(0xFFFFFFFFu - (unsigned)(2 * t));
    ull kB = ((ull)fenc(v1) << 32) | (ull)(0xFFFFFFFFu - (unsigned)(2 * t + 1));
    ull km = (kA > kB) ? kA : kB;
    #pragma unroll
    for (int o = 16; o; o >>= 1) {
      ull other = __shfl_xor_sync(0xffffffffu, km, o);
      if (other > km) km = other;
    }
    if (lane == 0) s_key[wid] = km;
    __syncthreads();
  }

  // ======== final selection ========
  {
    ull kk = s_key[0];
    #pragma unroll
    for (int i = 1; i < 8; i++) { ull o = s_key[i]; if (o > kk) kk = o; }
    int id = (int)(0xFFFFFFFFu - (unsigned)(kk & 0xFFFFFFFFull));
    if (wid == 0) sumr += s_kpT[lane * KPT_S + id] - 0.001953125f;
    if (t == 0) out[OFF_UNITS + (size_t)b * NSTEPS + (NSTEPS - 1)] = (float)id * sel;
  }
  if (wid == 0) s_sum[lane] = sumr;
  __syncthreads();

  // ======== epilogue ========
  for (int j = t; j < NAR; j += 256) {
    float acc0 = ar0[(size_t)b * NAR + j] + 64.0f * bp[j];
    float acc1 = 0.f, acc2 = 0.f, acc3 = 0.f;
    #pragma unroll
    for (int k = 0; k < 32; k += 4) {
      acc0 = fmaf(s_sum[k + 0], Wp[(size_t)(k + 0) * NAR + j], acc0);
      acc1 = fmaf(s_sum[k + 1], Wp[(size_t)(k + 1) * NAR + j], acc1);
      acc2 = fmaf(s_sum[k + 2], Wp[(size_t)(k + 2) * NAR + j], acc2);
      acc3 = fmaf(s_sum[k + 3], Wp[(size_t)(k + 3) * NAR + j], acc3);
    }
    __stcs(out + OFF_AR + (size_t)b * NAR + j, ((acc0 + acc1) + (acc2 + acc3)) * sel);
  }
}

// ---------------- host threefry ----------------
static inline void h_tf2x32(uint32_t k0, uint32_t k1, uint32_t x0, uint32_t x1,
                            uint32_t &o0, uint32_t &o1) {
  uint32_t ks2 = k0 ^ k1 ^ 0x1BD11BDAu;
  x0 += k0; x1 += k1;
#define HRND(r) { x0 += x1; x1 = (x1 << (r)) | (x1 >> (32 - (r))); x1 ^= x0; }
  HRND(13) HRND(15) HRND(26) HRND(6)   x0 += k1;  x1 += ks2 + 1u;
  HRND(17) HRND(29) HRND(16) HRND(24)  x0 += ks2; x1 += k0  + 2u;
  HRND(13) HRND(15) HRND(26) HRND(6)   x0 += k0;  x1 += k1  + 3u;
  HRND(17) HRND(29) HRND(16) HRND(24)  x0 += k1;  x1 += ks2 + 4u;
  HRND(13) HRND(15) HRND(26) HRND(6)   x0 += ks2; x1 += k0  + 5u;
#undef HRND
  o0 = x0; o1 = x1;
}

// ---------------- launcher ----------------
extern "C" void kernel_launch(void* const* d_in, const int* in_sizes, int n_in,
                              void* d_out, int out_size) {
  const float* ar_in   = (const float*)d_in[0];
  const int*   action  = (const int*)  d_in[1];
  const float* emb     = (const float*)d_in[2];
  const float* Wf      = (const float*)d_in[3];
  const float* bf      = (const float*)d_in[4];
  const float* Wk      = (const float*)d_in[5];
  const float* bk      = (const float*)d_in[6];
  const float* W1      = (const float*)d_in[7];
  const float* b1      = (const float*)d_in[8];
  const float* W2      = (const float*)d_in[9];
  const float* b2      = (const float*)d_in[10];
  const float* Wx      = (const float*)d_in[11];
  const float* Wh      = (const float*)d_in[12];
  const float* bl      = (const float*)d_in[13];
  const float* Wp      = (const float*)d_in[14];
  const float* bp      = (const float*)d_in[15];
  const float* table   = (const float*)d_in[16];
  const float* selt    = (const float*)d_in[17];
  float* out = (float*)d_out;

  SubKeys sk;
  {
    uint32_t k0 = 0u, k1 = 42u;
    for (int s = 0; s < NSTEPS; s++) {
      uint32_t n0, n1, s0, s1;
      h_tf2x32(k0, k1, 0u, 0u, n0, n1);
      h_tf2x32(k0, k1, 0u, 1u, s0, s1);
      sk.a[s] = s0; sk.b[s] = s1;
      k0 = n0; k1 = n1;
    }
  }

  cudaFuncSetAttribute(persist_kernel, cudaFuncAttributeMaxDynamicSharedMemorySize,
                       SMEM_FLOATS * (int)sizeof(float));

  precompute_kernel<<<34 + GEMM_BLKS + GUM_BLKS, 256>>>(Wp, bp, W1, ar_in, action, sk);
  persist_kernel<<<256, 256, SMEM_FLOATS * sizeof(float)>>>(
      ar_in, emb, Wf, bf, Wk, bk, W1, b1, W2, b2, Wx, Wh, bl, Wp, bp, table, selt, out);
}

// round 8
// speedup vs baseline: 6.6336x; 1.0365x over previous
#include <cuda_runtime.h>
#include <stdint.h>

#define NB 256
#define NE 512
#define NC 256
#define NAR 1024
#define NH 256
#define NK 32
#define NSTEPS 64

typedef unsigned long long ull;

// ---------------- static device scratch ----------------
__device__ float g_xpart[8 * NB * NH];
__device__ float g_WpW1[NK * NH];
__device__ float g_bpW1[NH];
__device__ float g_kpT[(size_t)NB * NE * NK];          // 16 MB, layout [b][e][h]
__device__ float g_func[NB * NH];
__device__ float g_gumbel[(size_t)NB * NSTEPS * NE];   // 32 MB, layout [b][s][e]
__device__ int   g_action[NB];

#define OFF_UNITS ((size_t)NB * NSTEPS * NE)
#define OFF_AR    (OFF_UNITS + (size_t)NB * NSTEPS)

struct SubKeys { unsigned int a[64]; unsigned int b[64]; };

// ---------------- f32x2 packed helpers ----------------
__device__ __forceinline__ void ffma2(ull &d, ull a, ull b) {
  asm("fma.rn.f32x2 %0, %1, %2, %3;" : "=l"(d) : "l"(a), "l"(b), "l"(d));
}
__device__ __forceinline__ ull fadd2(ull a, ull b) {
  ull r; asm("add.rn.f32x2 %0, %1, %2;" : "=l"(r) : "l"(a), "l"(b)); return r;
}
__device__ __forceinline__ ull dup2(float x) {
  ull r; asm("mov.b64 %0, {%1, %1};" : "=l"(r) : "f"(x)); return r;
}
__device__ __forceinline__ ull pack2(float x, float y) {
  ull r; asm("mov.b64 %0, {%1, %2};" : "=l"(r) : "f"(x), "f"(y)); return r;
}
__device__ __forceinline__ float2 unpack2(ull v) {
  float2 r; asm("mov.b64 {%0, %1}, %2;" : "=f"(r.x), "=f"(r.y) : "l"(v)); return r;
}

// ---------------- Threefry-2x32 (20 rounds), device ----------------
__device__ __forceinline__ void tf2x32(uint32_t k0, uint32_t k1,
                                       uint32_t x0, uint32_t x1,
                                       uint32_t &o0, uint32_t &o1) {
  uint32_t ks2 = k0 ^ k1 ^ 0x1BD11BDAu;
  x0 += k0; x1 += k1;
#define RND(r) { x0 += x1; x1 = __funnelshift_l(x1, x1, (r)); x1 ^= x0; }
  RND(13) RND(15) RND(26) RND(6)   x0 += k1;  x1 += ks2 + 1u;
  RND(17) RND(29) RND(16) RND(24)  x0 += ks2; x1 += k0  + 2u;
  RND(13) RND(15) RND(26) RND(6)   x0 += k0;  x1 += k1  + 3u;
  RND(17) RND(29) RND(16) RND(24)  x0 += k1;  x1 += ks2 + 4u;
  RND(13) RND(15) RND(26) RND(6)   x0 += ks2; x1 += k0  + 5u;
#undef RND
  o0 = x0; o1 = x1;
}

__device__ __forceinline__ float gumbelize(uint32_t bits) {
  float f = __uint_as_float((bits >> 9) | 0x3f800000u) - 1.0f;
  f = fmaxf(f, 1e-20f);
  return -__logf(-__logf(f));
}

__device__ __forceinline__ unsigned fenc(float f) {
  unsigned u = __float_as_uint(f);
  return (u & 0x80000000u) ? ~u : (u | 0x80000000u);
}

// ---------------- fused precompute ----------------
#define KP_BLKS   512
#define GEMM_BLKS 256
#define WPW1_BLKS 33
#define FUNC_BLKS 256
#define GUM_BLKS  8192
__global__ void precompute_kernel(const float* __restrict__ Wp, const float* __restrict__ bp,
                                  const float* __restrict__ W1, const float* __restrict__ ar0,
                                  const int* __restrict__ action_raw,
                                  const float* __restrict__ emb, const float* __restrict__ Wk,
                                  const float* __restrict__ bk, const float* __restrict__ Wf,
                                  const float* __restrict__ bf, const float* __restrict__ table,
                                  const float* __restrict__ b1,
                                  SubKeys sk) {
  __shared__ __align__(16) float psm[8192];
  int blk = blockIdx.x;
  int t = threadIdx.x;

  if (blk < KP_BLKS) {
    int b = blk >> 1, pass = blk & 1;
    for (int i = t; i < NC * NK; i += 256) psm[i] = Wk[i];
    __syncthreads();
    int hg = t & 3, rquad = t >> 2;
    int h0 = hg * 8;
    int r0 = pass * 256 + rquad * 4;
    ull bkp[4];
    #pragma unroll
    for (int j = 0; j < 4; j++) bkp[j] = pack2(bk[h0 + 2*j], bk[h0 + 2*j + 1]);
    ull acc[4][4];
    #pragma unroll
    for (int i = 0; i < 4; i++)
      #pragma unroll
      for (int j = 0; j < 4; j++) acc[i][j] = bkp[j];

    const float* e0p = emb + ((size_t)b * NE + r0) * NC;
    for (int c = 0; c < NC; c += 4) {
      float4 e0 = *(const float4*)(e0p + c);
      float4 e1 = *(const float4*)(e0p + NC + c);
      float4 e2 = *(const float4*)(e0p + 2 * NC + c);
      float4 e3 = *(const float4*)(e0p + 3 * NC + c);
      #pragma unroll
      for (int cc = 0; cc < 4; cc++) {
        const float* wp = psm + (c + cc) * 32 + h0;
        ull w0 = *(const ull*)(wp);
        ull w1 = *(const ull*)(wp + 2);
        ull w2 = *(const ull*)(wp + 4);
        ull w3 = *(const ull*)(wp + 6);
        ull a0 = dup2(((const float*)&e0)[cc]);
        ull a1 = dup2(((const float*)&e1)[cc]);
        ull a2 = dup2(((const float*)&e2)[cc]);
        ull a3 = dup2(((const float*)&e3)[cc]);
        ffma2(acc[0][0], a0, w0); ffma2(acc[0][1], a0, w1); ffma2(acc[0][2], a0, w2); ffma2(acc[0][3], a0, w3);
        ffma2(acc[1][0], a1, w0); ffma2(acc[1][1], a1, w1); ffma2(acc[1][2], a1, w2); ffma2(acc[1][3], a1, w3);
        ffma2(acc[2][0], a2, w0); ffma2(acc[2][1], a2, w1); ffma2(acc[2][2], a2, w2); ffma2(acc[2][3], a2, w3);
        ffma2(acc[3][0], a3, w0); ffma2(acc[3][1], a3, w1); ffma2(acc[3][2], a3, w2); ffma2(acc[3][3], a3, w3);
      }
    }
    float* kpb = g_kpT + (size_t)b * (NE * NK);
    #pragma unroll
    for (int i = 0; i < 4; i++)
      #pragma unroll
      for (int j = 0; j < 4; j++)
        *(ull*)(kpb + (size_t)(r0 + i) * NK + h0 + 2 * j) = acc[i][j];
  } else if (blk < KP_BLKS + GEMM_BLKS) {
    int flat = blk - KP_BLKS;
    int bx = flat & 3, by = (flat >> 2) & 7, bz = flat >> 5;
    float* As = psm;
    float* Bs = psm + 528;
    int bm = by * 32, bn = bx * 64, k0 = bz * 128;
    int ty = t >> 4, tx = t & 15;
    float acc[2][4] = {{0.f,0.f,0.f,0.f},{0.f,0.f,0.f,0.f}};
    for (int kc = 0; kc < 128; kc += 16) {
      {
        int m = t >> 3;
        int kk = (t & 7) * 2;
        const float* p = ar0 + (size_t)(bm + m) * NAR + (k0 + kc + kk);
        As[kk * 33 + m] = p[0];
        As[(kk + 1) * 33 + m] = p[1];
      }
      {
        int kk = t >> 4;
        int j = (t & 15) * 4;
        const float* p = W1 + (size_t)(k0 + kc + kk) * NH + bn + j;
        Bs[kk * 68 + j] = p[0]; Bs[kk * 68 + j+1] = p[1]; Bs[kk * 68 + j+2] = p[2]; Bs[kk * 68 + j+3] = p[3];
      }
      __syncthreads();
      #pragma unroll
      for (int k = 0; k < 16; k++) {
        float a0 = As[k * 33 + ty * 2], a1 = As[k * 33 + ty * 2 + 1];
        float4 bv = *reinterpret_cast<const float4*>(&Bs[k * 68 + tx * 4]);
        acc[0][0] += a0 * bv.x; acc[0][1] += a0 * bv.y; acc[0][2] += a0 * bv.z; acc[0][3] += a0 * bv.w;
        acc[1][0] += a1 * bv.x; acc[1][1] += a1 * bv.y; acc[1][2] += a1 * bv.z; acc[1][3] += a1 * bv.w;
      }
      __syncthreads();
    }
    float* xp = g_xpart + (size_t)bz * (NB * NH);
    #pragma unroll
    for (int im = 0; im < 2; im++) {
      int row = bm + ty * 2 + im;
      float* o = xp + (size_t)row * NH + bn + tx * 4;
      float bb0 = (bz == 0) ? b1[bn + tx * 4]     : 0.f;
      float bb1 = (bz == 0) ? b1[bn + tx * 4 + 1] : 0.f;
      float bb2 = (bz == 0) ? b1[bn + tx * 4 + 2] : 0.f;
      float bb3 = (bz == 0) ? b1[bn + tx * 4 + 3] : 0.f;
      o[0] = acc[im][0] + bb0; o[1] = acc[im][1] + bb1;
      o[2] = acc[im][2] + bb2; o[3] = acc[im][3] + bb3;
    }
  } else if (blk < KP_BLKS + GEMM_BLKS + WPW1_BLKS) {
    float* s_row = psm;
    int i = blk - (KP_BLKS + GEMM_BLKS);
    for (int k = t; k < NAR; k += 256)
      s_row[k] = (i < NK) ? Wp[(size_t)i * NAR + k] : bp[k];
    __syncthreads();
    float a0 = 0.f, a1 = 0.f, a2 = 0.f, a3 = 0.f;
    for (int k = 0; k < NAR; k += 4) {
      a0 += s_row[k]     * W1[(size_t)k * NH + t];
      a1 += s_row[k + 1] * W1[(size_t)(k + 1) * NH + t];
      a2 += s_row[k + 2] * W1[(size_t)(k + 2) * NH + t];
      a3 += s_row[k + 3] * W1[(size_t)(k + 3) * NH + t];
    }
    float acc = (a0 + a1) + (a2 + a3);
    if (i < NK) g_WpW1[i * NH + t] = acc; else g_bpW1[t] = acc;
  } else if (blk == KP_BLKS + GEMM_BLKS + WPW1_BLKS) {
    int odd = (t < 128) ? action_raw[2 * t + 1] : 0;
    int any = __syncthreads_or(odd != 0);
    g_action[t] = any ? action_raw[t] : action_raw[2 * t];
  } else if (blk < KP_BLKS + GEMM_BLKS + WPW1_BLKS + 1 + FUNC_BLKS) {
    int b = blk - (KP_BLKS + GEMM_BLKS + WPW1_BLKS + 1);
    int odd = (t < 128) ? action_raw[2 * t + 1] : 0;
    int any = __syncthreads_or(odd != 0);
    int a = any ? action_raw[b] : action_raw[2 * b];
    psm[t] = table[(size_t)a * 256 + t];
    __syncthreads();
    float a0 = 0.f, a1 = 0.f;
    #pragma unroll 4
    for (int k = 0; k < 256; k += 2) {
      a0 = fmaf(psm[k],     Wf[(size_t)k * 256 + t], a0);
      a1 = fmaf(psm[k + 1], Wf[(size_t)(k + 1) * 256 + t], a1);
    }
    g_func[b * 256 + t] = fmaxf(bf[t] + a0 + a1, 0.0f);
  } else {
    int gi = blk - (KP_BLKS + GEMM_BLKS + WPW1_BLKS + 1 + FUNC_BLKS);
    int v0 = gi * 1024 + t * 4;
    int b = v0 >> 15;
    int rem = v0 & 32767;
    int s = rem >> 9;
    int e = rem & 511;
    int j = b * 512 + e;
    uint32_t k0 = sk.a[s], k1 = sk.b[s];
    float4 r;
    uint32_t o0, o1;
    tf2x32(k0, k1, 0u, (uint32_t)j,     o0, o1); r.x = gumbelize(o0 ^ o1);
    tf2x32(k0, k1, 0u, (uint32_t)(j+1), o0, o1); r.y = gumbelize(o0 ^ o1);
    tf2x32(k0, k1, 0u, (uint32_t)(j+2), o0, o1); r.z = gumbelize(o0 ^ o1);
    tf2x32(k0, k1, 0u, (uint32_t)(j+3), o0, o1); r.w = gumbelize(o0 ^ o1);
    *(float4*)(g_gumbel + (size_t)v0) = r;
  }
}

// ---------------- persistent per-batch kernel ----------------
#define KPT_S    514
#define OFF_KPT  0
#define OFF_WXH  16448
#define OFF_ZR   24704
#define OFF_T    24960
#define OFF_PART 25216
#define OFF_H    25344
#define OFF_HD   25376
#define OFF_RED  25440
#define OFF_KEY  25456
#define OFF_SUM  25472
#define SMEM_FLOATS 25504

__global__ __launch_bounds__(256, 2) void persist_kernel(
    const float* __restrict__ ar0,
    const float* __restrict__ W2, const float* __restrict__ b2,
    const float* __restrict__ Wx, const float* __restrict__ Wh,
    const float* __restrict__ bl, const float* __restrict__ Wp,
    const float* __restrict__ bp,
    const float* __restrict__ selt, float* __restrict__ out)
{
  extern __shared__ float sm[];
  float* s_kpT  = sm + OFF_KPT;
  float* s_Wxh  = sm + OFF_WXH;
  float* s_zred = sm + OFF_ZR;
  float* s_t    = sm + OFF_T;
  float* s_part = sm + OFF_PART;
  float* s_h    = sm + OFF_H;
  ull*   s_hd   = (ull*)(sm + OFF_HD);
  float* s_red  = sm + OFF_RED;
  ull*   s_key  = (ull*)(sm + OFF_KEY);
  float* s_sum  = sm + OFF_SUM;

  int b = blockIdx.x, t = threadIdx.x;
  int lane = t & 31, wid = t >> 5;

  float sel = selt[g_action[b]];

  // ======== prologue ========
  {
    const float* kpg = g_kpT + (size_t)b * (NE * NK);
    #pragma unroll
    for (int i = t * 4; i < NE * NK; i += 1024) {
      float4 v = *(const float4*)(kpg + i);
      int e = i >> 5, h = i & 31;
      s_kpT[(h + 0) * KPT_S + e] = v.x;
      s_kpT[(h + 1) * KPT_S + e] = v.y;
      s_kpT[(h + 2) * KPT_S + e] = v.z;
      s_kpT[(h + 3) * KPT_S + e] = v.w;
    }
  }
  for (int i = t; i < 4096; i += 256) {
    int k = i >> 7, col = i & 127;
    int g = col >> 5, h = col & 31;
    s_Wxh[k * 258 + h * 8 + g * 2]     = Wx[i];
    s_Wxh[k * 258 + h * 8 + g * 2 + 1] = Wh[i];
  }
  if (t < 32) { s_h[t] = 0.0f; s_hd[t] = 0ull; }

  float func_r = g_func[b * 256 + t];
  float x_r = g_xpart[b * NH + t];      // includes b1 (folded in precompute)
  #pragma unroll
  for (int p = 1; p < 8; p++) x_r += g_xpart[p * (NB * NH) + b * NH + t];

  float wpw1r[32];
  ull w2p[16];
  float csum = 0.f;
  #pragma unroll
  for (int k = 0; k < 32; k++) { wpw1r[k] = g_WpW1[k * NH + t]; csum += wpw1r[k]; }
  #pragma unroll
  for (int j = 0; j < 16; j++)
    w2p[j] = pack2(W2[(size_t)(wid * 32 + 2*j) * 32 + lane],
                   W2[(size_t)(wid * 32 + 2*j + 1) * 32 + lane]);
  float bpw1c = g_bpW1[t] - 0.001953125f * csum;
  float b2r = b2[lane];

  int khalf = wid >> 2;
  int lh = (wid & 3) * 8 + (lane >> 2);
  int lg = lane & 3;
  float blr = bl[lg * 32 + lh];
  float creg = 0.f, sumr = 0.f;
  float m0 = 1.0f, m1 = 1.0f;
  __syncthreads();

  const float* gumbase = g_gumbel + (size_t)b * (NSTEPS * NE) + 2 * t;

  // ======== 64-step loop ========
  for (int s = 0; s < NSTEPS; s++) {
    float2 gpair = *(const float2*)(gumbase + s * NE);
    float hpreg = s_h[lane];

    if (s > 0) {
      ull kk = s_key[0];
      #pragma unroll
      for (int i = 1; i < 8; i++) { ull o = s_key[i]; if (o > kk) kk = o; }
      int id = (int)(0xFFFFFFFFu - (unsigned)(kk & 0xFFFFFFFFull));
      if (id == 2 * t) m0 = 0.0f;
      if (id == 2 * t + 1) m1 = 0.0f;
      const float* kc = s_kpT + id;
      float xv0 = x_r + bpw1c, xv1 = 0.f, xv2 = 0.f, xv3 = 0.f;
      #pragma unroll
      for (int k = 0; k < 32; k += 4) {
        xv0 = fmaf(kc[(k + 0) * KPT_S], wpw1r[k + 0], xv0);
        xv1 = fmaf(kc[(k + 1) * KPT_S], wpw1r[k + 1], xv1);
        xv2 = fmaf(kc[(k + 2) * KPT_S], wpw1r[k + 2], xv2);
        xv3 = fmaf(kc[(k + 3) * KPT_S], wpw1r[k + 3], xv3);
      }
      x_r = (xv0 + xv1) + (xv2 + xv3);
      if (wid == 0) sumr += s_kpT[lane * KPT_S + id] - 0.001953125f;
      if (t == 0) out[OFF_UNITS + (size_t)b * NSTEPS + (s - 1)] = (float)id * sel;
    }
    float tval = fmaxf(func_r + x_r, 0.0f);
    s_t[t] = tval;
    __syncwarp();
    {
      const ull* tp = (const ull*)(s_t + wid * 32);
      ull za = 0ull, zb = 0ull;
      #pragma unroll
      for (int j = 0; j < 16; j += 2) {
        ffma2(za, tp[j], w2p[j]);
        ffma2(zb, tp[j + 1], w2p[j + 1]);
      }
      float2 zv = unpack2(fadd2(za, zb));
      s_zred[t] = zv.x + zv.y;
    }
    __syncthreads();

    float z2l;
    {
      float r0 = s_zred[lane]        + s_zred[32 + lane];
      float r1 = s_zred[64 + lane]   + s_zred[96 + lane];
      float r2 = s_zred[128 + lane]  + s_zred[160 + lane];
      float r3 = s_zred[192 + lane]  + s_zred[224 + lane];
      z2l = b2r + ((r0 + r1) + (r2 + r3));
    }
    {
      float accA = (khalf == 0) ? blr : 0.f, accB = 0.f;
      const float* wbase = s_Wxh + lh * 8 + lg * 2 + khalf * (16 * 258);
      #pragma unroll
      for (int k16 = 0; k16 < 16; k16 += 2) {
        int k = khalf * 16 + k16;
        float z2a = __shfl_sync(0xffffffffu, z2l, k);
        float ha  = __shfl_sync(0xffffffffu, hpreg, k);
        float2 wa = unpack2(*(const ull*)(wbase + k16 * 258));
        accA = fmaf(z2a, wa.x, fmaf(ha, wa.y, accA));
        float z2b = __shfl_sync(0xffffffffu, z2l, k + 1);
        float hb  = __shfl_sync(0xffffffffu, hpreg, k + 1);
        float2 wb = unpack2(*(const ull*)(wbase + (k16 + 1) * 258));
        accB = fmaf(z2b, wb.x, fmaf(hb, wb.y, accB));
      }
      float acc = accA + accB;
      if (khalf == 1) s_part[lh * 4 + lg] = acc;
      __syncthreads();
      if (khalf == 0) {
        acc += s_part[lh * 4 + lg];
        float e2 = __expf((lg == 2) ? (2.f * acc) : (-acc));
        float tg = (lg == 2) ? (1.f - __fdividef(2.f, e2 + 1.f))
                             : __fdividef(1.f, 1.f + e2);
        int base = lane & ~3;
        float iv = __shfl_sync(0xffffffffu, tg, base);
        float fv = __shfl_sync(0xffffffffu, tg, base + 1);
        float gv = __shfl_sync(0xffffffffu, tg, base + 2);
        float ov = __shfl_sync(0xffffffffu, tg, base + 3);
        creg = fv * creg + iv * gv;
        float e2c = __expf(2.f * creg);
        float hv = ov * (1.f - __fdividef(2.f, e2c + 1.f));
        if (lg == 0) { s_h[lh] = hv; s_hd[lh] = dup2(hv); }
      }
    }
    __syncthreads();

    ull a0 = 0ull, a1 = 0ull, a2 = 0ull, a3 = 0ull;
    {
      const float* kb = s_kpT + 2 * t;
      #pragma unroll
      for (int q = 0; q < 8; q++) {
        ffma2(a0, *(const ull*)(kb + (4*q + 0) * KPT_S), s_hd[4*q + 0]);
        ffma2(a1, *(const ull*)(kb + (4*q + 1) * KPT_S), s_hd[4*q + 1]);
        ffma2(a2, *(const ull*)(kb + (4*q + 2) * KPT_S), s_hd[4*q + 2]);
        ffma2(a3, *(const ull*)(kb + (4*q + 3) * KPT_S), s_hd[4*q + 3]);
      }
    }
    float2 yv = unpack2(fadd2(fadd2(a0, a1), fadd2(a2, a3)));
    float y0 = yv.x * m0, y1 = yv.y * m1;
    __stcs((float2*)(out + ((size_t)b * NSTEPS + s) * NE + 2 * t),
           make_float2(y0 * sel, y1 * sel));
    float p0 = __expf(y0), p1 = __expf(y1);
    float ssum = p0 + p1;
    #pragma unroll
    for (int o = 16; o; o >>= 1) ssum += __shfl_xor_sync(0xffffffffu, ssum, o);
    if (lane == 0) s_red[wid] = ssum;
    __syncthreads();

    float S;
    {
      float r0 = s_red[0] + s_red[1], r1 = s_red[2] + s_red[3];
      float r2 = s_red[4] + s_red[5], r3 = s_red[6] + s_red[7];
      S = (r0 + r1) + (r2 + r3);
    }
    float v0 = fmaf(S, gpair.x, p0);
    float v1 = fmaf(S, gpair.y, p1);
    ull kA = ((ull)fenc(v0) << 32) | (ull)(0xFFFFFFFFu - (unsigned)(2 * t));
    ull kB = ((ull)fenc(v1) << 32) | (ull)(0xFFFFFFFFu - (unsigned)(2 * t + 1));
    ull km = (kA > kB) ? kA : kB;
    #pragma unroll
    for (int o = 16; o; o >>= 1) {
      ull other = __shfl_xor_sync(0xffffffffu, km, o);
      if (other > km) km = other;
    }
    if (lane == 0) s_key[wid] = km;
    __syncthreads();
  }

  // ======== final selection ========
  {
    ull kk = s_key[0];
    #pragma unroll
    for (int i = 1; i < 8; i++) { ull o = s_key[i]; if (o > kk) kk = o; }
    int id = (int)(0xFFFFFFFFu - (unsigned)(kk & 0xFFFFFFFFull));
    if (wid == 0) sumr += s_kpT[lane * KPT_S + id] - 0.001953125f;
    if (t == 0) out[OFF_UNITS + (size_t)b * NSTEPS + (NSTEPS - 1)] = (float)id * sel;
  }
  if (wid == 0) s_sum[lane] = sumr;
  __syncthreads();

  // ======== epilogue ========
  for (int j = t; j < NAR; j += 256) {
    float acc0 = ar0[(size_t)b * NAR + j] + 64.0f * bp[j];
    float acc1 = 0.f, acc2 = 0.f, acc3 = 0.f;
    #pragma unroll
    for (int k = 0; k < 32; k += 4) {
      acc0 = fmaf(s_sum[k + 0], Wp[(size_t)(k + 0) * NAR + j], acc0);
      acc1 = fmaf(s_sum[k + 1], Wp[(size_t)(k + 1) * NAR + j], acc1);
      acc2 = fmaf(s_sum[k + 2], Wp[(size_t)(k + 2) * NAR + j], acc2);
      acc3 = fmaf(s_sum[k + 3], Wp[(size_t)(k + 3) * NAR + j], acc3);
    }
    __stcs(out + OFF_AR + (size_t)b * NAR + j, ((acc0 + acc1) + (acc2 + acc3)) * sel);
  }
}

// ---------------- host threefry ----------------
static inline void h_tf2x32(uint32_t k0, uint32_t k1, uint32_t x0, uint32_t x1,
                            uint32_t &o0, uint32_t &o1) {
  uint32_t ks2 = k0 ^ k1 ^ 0x1BD11BDAu;
  x0 += k0; x1 += k1;
#define HRND(r) { x0 += x1; x1 = (x1 << (r)) | (x1 >> (32 - (r))); x1 ^= x0; }
  HRND(13) HRND(15) HRND(26) HRND(6)   x0 += k1;  x1 += ks2 + 1u;
  HRND(17) HRND(29) HRND(16) HRND(24)  x0 += ks2; x1 += k0  + 2u;
  HRND(13) HRND(15) HRND(26) HRND(6)   x0 += k0;  x1 += k1  + 3u;
  HRND(17) HRND(29) HRND(16) HRND(24)  x0 += k1;  x1 += ks2 + 4u;
  HRND(13) HRND(15) HRND(26) HRND(6)   x0 += ks2; x1 += k0  + 5u;
#undef HRND
  o0 = x0; o1 = x1;
}

// ---------------- launcher ----------------
extern "C" void kernel_launch(void* const* d_in, const int* in_sizes, int n_in,
                              void* d_out, int out_size) {
  const float* ar_in   = (const float*)d_in[0];
  const int*   action  = (const int*)  d_in[1];
  const float* emb     = (const float*)d_in[2];
  const float* Wf      = (const float*)d_in[3];
  const float* bf      = (const float*)d_in[4];
  const float* Wk      = (const float*)d_in[5];
  const float* bk      = (const float*)d_in[6];
  const float* W1      = (const float*)d_in[7];
  const float* b1      = (const float*)d_in[8];
  const float* W2      = (const float*)d_in[9];
  const float* b2      = (const float*)d_in[10];
  const float* Wx      = (const float*)d_in[11];
  const float* Wh      = (const float*)d_in[12];
  const float* bl      = (const float*)d_in[13];
  const float* Wp      = (const float*)d_in[14];
  const float* bp      = (const float*)d_in[15];
  const float* table   = (const float*)d_in[16];
  const float* selt    = (const float*)d_in[17];
  float* out = (float*)d_out;

  SubKeys sk;
  {
    uint32_t k0 = 0u, k1 = 42u;
    for (int s = 0; s < NSTEPS; s++) {
      uint32_t n0, n1, s0, s1;
      h_tf2x32(k0, k1, 0u, 0u, n0, n1);
      h_tf2x32(k0, k1, 0u, 1u, s0, s1);
      sk.a[s] = s0; sk.b[s] = s1;
      k0 = n0; k1 = n1;
    }
  }

  cudaFuncSetAttribute(persist_kernel, cudaFuncAttributeMaxDynamicSharedMemorySize,
                       SMEM_FLOATS * (int)sizeof(float));

  precompute_kernel<<<KP_BLKS + GEMM_BLKS + WPW1_BLKS + 1 + FUNC_BLKS + GUM_BLKS, 256>>>(
      Wp, bp, W1, ar_in, action, emb, Wk, bk, Wf, bf, table, b1, sk);
  persist_kernel<<<256, 256, SMEM_FLOATS * sizeof(float)>>>(
      ar_in, W2, b2, Wx, Wh, bl, Wp, bp, selt, out);
}